// round 1
// baseline (speedup 1.0000x reference)
#include <cuda_runtime.h>
#include <math.h>

#define NB    128
#define NTOKN 64
#define CDIM  784
#define NHD   8
#define HD    98
#define HID   3136
#define NROW  (NB*NTOKN)      // 8192
#define M2    (NB*784)        // 100352
#define OUT1  (NROW*CDIM)     // 6422528

// ---------------- scratch (device globals; no allocation allowed) ----------
__device__ float g_h     [NROW*CDIM];
__device__ float g_qkv   [NROW*3*CDIM];
__device__ float g_aomain[NROW*CDIM];
__device__ float g_o     [NROW*CDIM];
__device__ float g_xr    [NROW*CDIM];
__device__ float g_h2    [NROW*CDIM];
__device__ float g_mid   [NROW*HID];
__device__ float g_xT    [M2*64];
__device__ float g_bfqkv [M2*192];
__device__ float g_bfao  [M2*64];
__device__ float g_bf2   [M2*64];
__device__ float g_wqkvT [64*192];
__device__ float g_woutT [64*64];
__device__ float g_qr    [NB*49*64];
__device__ float g_kr    [NB*49*64];
__device__ float g_ar    [NB*49*49];
__device__ int   g_topk  [NB*49*4];

// ---------------- LayerNorm: one block per row -----------------------------
__global__ void ln_kernel(const float* __restrict__ x, const float* __restrict__ g,
                          const float* __restrict__ b, float* __restrict__ y) {
    int row = blockIdx.x;
    const float* xr = x + (size_t)row * CDIM;
    float* yr = y + (size_t)row * CDIM;
    float s = 0.f, s2 = 0.f;
    for (int i = threadIdx.x; i < CDIM; i += blockDim.x) {
        float v = xr[i]; s += v; s2 += v * v;
    }
    for (int o = 16; o; o >>= 1) {
        s  += __shfl_xor_sync(0xffffffffu, s,  o);
        s2 += __shfl_xor_sync(0xffffffffu, s2, o);
    }
    __shared__ float sh[16], sh2[16];
    int warp = threadIdx.x >> 5, lane = threadIdx.x & 31;
    if (lane == 0) { sh[warp] = s; sh2[warp] = s2; }
    __syncthreads();
    if (threadIdx.x == 0) {
        float t = 0.f, t2 = 0.f;
        int nw = blockDim.x >> 5;
        for (int i = 0; i < nw; i++) { t += sh[i]; t2 += sh2[i]; }
        sh[0] = t; sh2[0] = t2;
    }
    __syncthreads();
    float mean = sh[0] * (1.0f / CDIM);
    float var  = sh2[0] * (1.0f / CDIM) - mean * mean;
    float rinv = rsqrtf(var + 1e-5f);
    for (int i = threadIdx.x; i < CDIM; i += blockDim.x)
        yr[i] = (xr[i] - mean) * rinv * g[i] + b[i];
}

// ---------------- generic tiled SGEMM: C = A(MxK) @ B(KxN) + epilogue ------
// act: 0 = none, 1 = exact GELU. bias/res may be null.
// Requires: M % 128 == 0, K % 8 == 0, N % 4 == 0.
__global__ void __launch_bounds__(256)
sgemm_kernel(const float* __restrict__ A, const float* __restrict__ B,
             const float* __restrict__ bias, const float* __restrict__ res,
             float* __restrict__ C, int M, int N, int K, int act) {
    __shared__ float As[8][128];
    __shared__ float Bs[8][128];
    int tid = threadIdx.x;
    int row0 = blockIdx.y * 128, col0 = blockIdx.x * 128;
    int tx = tid & 15, ty = tid >> 4;
    int tm0 = ty * 8, tn0 = tx * 8;
    float acc[8][8];
#pragma unroll
    for (int i = 0; i < 8; i++)
#pragma unroll
        for (int j = 0; j < 8; j++) acc[i][j] = 0.f;

    int aRow = tid >> 1,  aCol = (tid & 1) * 4;
    int bRow = tid >> 5,  bCol = (tid & 31) * 4;
    const float* Aptr = A + (size_t)(row0 + aRow) * K + aCol;
    const float* Bptr = B + (size_t)bRow * N + col0 + bCol;
    bool bIn = (col0 + bCol) < N;

    for (int k0 = 0; k0 < K; k0 += 8) {
        float4 av = *(const float4*)Aptr;
        float4 bv = bIn ? *(const float4*)Bptr : make_float4(0.f, 0.f, 0.f, 0.f);
        As[aCol + 0][aRow] = av.x;
        As[aCol + 1][aRow] = av.y;
        As[aCol + 2][aRow] = av.z;
        As[aCol + 3][aRow] = av.w;
        *(float4*)(&Bs[bRow][bCol]) = bv;
        __syncthreads();
#pragma unroll
        for (int k = 0; k < 8; k++) {
            float ar[8], br[8];
#pragma unroll
            for (int i = 0; i < 8; i++) ar[i] = As[k][tm0 + i];
#pragma unroll
            for (int j = 0; j < 8; j++) br[j] = Bs[k][tn0 + j];
#pragma unroll
            for (int i = 0; i < 8; i++)
#pragma unroll
                for (int j = 0; j < 8; j++)
                    acc[i][j] = fmaf(ar[i], br[j], acc[i][j]);
        }
        __syncthreads();
        Aptr += 8;
        Bptr += (size_t)8 * N;
    }

#pragma unroll
    for (int i = 0; i < 8; i++) {
        int r = row0 + tm0 + i;
#pragma unroll
        for (int j = 0; j < 8; j++) {
            int c = col0 + tn0 + j;
            if (c < N) {
                float v = acc[i][j];
                if (bias) v += bias[c];
                if (act == 1) v = 0.5f * v * (1.f + erff(v * 0.70710678118654752f));
                if (res) v += res[(size_t)r * N + c];
                C[(size_t)r * N + c] = v;
            }
        }
    }
}

// ---------------- fused main MHA: one block per (b, h) ---------------------
// smem: Q,K,V [64][99] + S [64][64]
#define ATTN_SMEM ((3*64*99 + 64*64) * 4)
__global__ void attn_kernel(const float* __restrict__ qkv, float* __restrict__ out) {
    extern __shared__ float sm[];
    float* Qs = sm;
    float* Ks = Qs + 64 * 99;
    float* Vs = Ks + 64 * 99;
    float* Ss = Vs + 64 * 99;
    int b = blockIdx.x >> 3;
    int h = blockIdx.x & 7;
    const float* base = qkv + (size_t)b * 64 * (3 * CDIM) + h * HD;

    for (int e = threadIdx.x; e < 64 * HD; e += blockDim.x) {
        int r = e / HD, d = e % HD;
        const float* rp = base + (size_t)r * (3 * CDIM) + d;
        Qs[r * 99 + d] = rp[0];
        Ks[r * 99 + d] = rp[CDIM];
        Vs[r * 99 + d] = rp[2 * CDIM];
    }
    __syncthreads();

    const float scale = 1.0f / sqrtf(98.0f);
    for (int e = threadIdx.x; e < 4096; e += blockDim.x) {
        int i = e >> 6, j = e & 63;
        const float* qi = Qs + i * 99;
        const float* kj = Ks + j * 99;
        float a = 0.f;
#pragma unroll
        for (int d = 0; d < HD; d++) a = fmaf(qi[d], kj[d], a);
        Ss[e] = a * scale;
    }
    __syncthreads();

    int warp = threadIdx.x >> 5, lane = threadIdx.x & 31;
    for (int i = warp; i < 64; i += 8) {
        float v0 = Ss[i * 64 + lane], v1 = Ss[i * 64 + lane + 32];
        float mx = fmaxf(v0, v1);
        for (int o = 16; o; o >>= 1) mx = fmaxf(mx, __shfl_xor_sync(0xffffffffu, mx, o));
        float e0 = __expf(v0 - mx), e1 = __expf(v1 - mx);
        float s = e0 + e1;
        for (int o = 16; o; o >>= 1) s += __shfl_xor_sync(0xffffffffu, s, o);
        float inv = 1.f / s;
        Ss[i * 64 + lane]      = e0 * inv;
        Ss[i * 64 + lane + 32] = e1 * inv;
    }
    __syncthreads();

    for (int e = threadIdx.x; e < 64 * HD; e += blockDim.x) {
        int i = e / HD, d = e % HD;
        const float* p = Ss + i * 64;
        float a = 0.f;
#pragma unroll
        for (int j = 0; j < 64; j++) a = fmaf(p[j], Vs[j * 99 + d], a);
        out[((size_t)b * 64 + i) * CDIM + h * HD + d] = a;
    }
}

// ---------------- elementwise add ------------------------------------------
__global__ void add_kernel(const float* __restrict__ a, const float* __restrict__ b,
                           float* __restrict__ c, int n) {
    int i = blockIdx.x * blockDim.x + threadIdx.x;
    if (i < n) c[i] = a[i] + b[i];
}

// ---------------- per-batch tiled transpose: [bt][R][Cc] -> [bt][Cc][R] -----
__global__ void transpose_kernel(const float* __restrict__ in, float* __restrict__ out,
                                 int R, int Cc) {
    __shared__ float tile[32][33];
    int b = blockIdx.z;
    int r0 = blockIdx.y * 32, c0 = blockIdx.x * 32;
    const float* ib = in + (size_t)b * R * Cc;
    float* ob = out + (size_t)b * R * Cc;
    int r = r0 + threadIdx.y, c = c0 + threadIdx.x;
    if (r < R && c < Cc) tile[threadIdx.y][threadIdx.x] = ib[(size_t)r * Cc + c];
    __syncthreads();
    int rr = r0 + threadIdx.x, cc = c0 + threadIdx.y;
    if (rr < R && cc < Cc) ob[(size_t)cc * R + rr] = tile[threadIdx.x][threadIdx.y];
}

// ---------------- small weight transpose: w[O][Cn] -> wt[Cn][O] -------------
__global__ void wtrans_kernel(const float* __restrict__ w, float* __restrict__ wt,
                              int O, int Cn) {
    int e = blockIdx.x * blockDim.x + threadIdx.x;
    if (e < O * Cn) { int o = e / Cn, c = e % Cn; wt[c * O + o] = w[e]; }
}

// ---------------- BiFormer: region mean-pool of q/k -------------------------
// qkvt: [b*784][192]; qr/kr: [b*49][64]
__global__ void bf_pool_kernel(const float* __restrict__ qkvt,
                               float* __restrict__ qr, float* __restrict__ kr) {
    int br = blockIdx.x;            // b*49 + r
    int b = br / 49, r = br % 49;
    int rh = r / 7, rw = r % 7;
    int tid = threadIdx.x;          // 128
    int c = tid & 63;
    int off = (tid >= 64) ? 64 : 0;
    int hw0 = (rh * 4) * 28 + rw * 4;
    float s = 0.f;
#pragma unroll
    for (int p = 0; p < 4; p++)
#pragma unroll
        for (int q = 0; q < 4; q++) {
            int hw = hw0 + p * 28 + q;
            s += qkvt[((size_t)b * 784 + hw) * 192 + off + c];
        }
    float* dst = (tid >= 64) ? kr : qr;
    dst[((size_t)b * 49 + r) * 64 + c] = s * (1.0f / 16.0f);
}

// ---------------- region affinity a_r[b][r][s] -------------------------------
__global__ void bf_ar_kernel(const float* __restrict__ qr, const float* __restrict__ kr,
                             float* __restrict__ ar) {
    int idx = blockIdx.x * blockDim.x + threadIdx.x;
    if (idx >= NB * 49 * 49) return;
    int s = idx % 49, r = (idx / 49) % 49, b = idx / (49 * 49);
    const float* qp = qr + ((size_t)b * 49 + r) * 64;
    const float* kp = kr + ((size_t)b * 49 + s) * 64;
    float a = 0.f;
#pragma unroll
    for (int c = 0; c < 64; c++) a = fmaf(qp[c], kp[c], a);
    ar[idx] = a;
}

// ---------------- top-4 per (b, r) (ties -> lower index, like lax.top_k) -----
__global__ void bf_topk_kernel(const float* __restrict__ ar, int* __restrict__ idx) {
    int t = blockIdx.x * blockDim.x + threadIdx.x;
    if (t >= NB * 49) return;
    float v[49];
    const float* row = ar + (size_t)t * 49;
#pragma unroll
    for (int s = 0; s < 49; s++) v[s] = row[s];
    for (int k = 0; k < 4; k++) {
        float best = -3.4e38f; int bi = 0;
        for (int s = 0; s < 49; s++)
            if (v[s] > best) { best = v[s]; bi = s; }
        idx[t * 4 + k] = bi;
        v[bi] = -3.4e38f;
    }
}

// ---------------- BiFormer region attention: one block per (b, m, r) ---------
__global__ void bf_attn_kernel(const float* __restrict__ qkvt, const int* __restrict__ idx,
                               float* __restrict__ ao) {
    __shared__ float Qs[16][8], Ks[64][9], Vs[64][9], S[16][64];
    __shared__ int sreg[4];
    int r = blockIdx.x % 49;
    int m = (blockIdx.x / 49) & 7;
    int b = blockIdx.x / (49 * 8);
    int tid = threadIdx.x;                 // 128
    int rh = r / 7, rw = r % 7;

    if (tid < 4) sreg[tid] = idx[((size_t)b * 49 + r) * 4 + tid];
    {
        int p = tid >> 3, d = tid & 7;
        int hw = (rh * 4 + (p >> 2)) * 28 + rw * 4 + (p & 3);
        Qs[p][d] = qkvt[((size_t)b * 784 + hw) * 192 + m * 8 + d];
    }
    __syncthreads();

    for (int e = tid; e < 512; e += 128) {
        int slot = e >> 3, d = e & 7;
        int t = slot >> 4, s = slot & 15;
        int sr = sreg[t];
        int hw = ((sr / 7) * 4 + (s >> 2)) * 28 + (sr % 7) * 4 + (s & 3);
        const float* p = qkvt + ((size_t)b * 784 + hw) * 192 + m * 8 + d;
        Ks[slot][d] = p[64];
        Vs[slot][d] = p[128];
    }
    __syncthreads();

    for (int e = tid; e < 1024; e += 128) {
        int i = e >> 6, j = e & 63;
        float a = 0.f;
#pragma unroll
        for (int d = 0; d < 8; d++) a = fmaf(Qs[i][d], Ks[j][d], a);
        S[i][j] = a * 0.125f;
    }
    __syncthreads();

    int warp = tid >> 5, lane = tid & 31;
    for (int i = warp; i < 16; i += 4) {
        float v0 = S[i][lane], v1 = S[i][lane + 32];
        float mx = fmaxf(v0, v1);
        for (int o = 16; o; o >>= 1) mx = fmaxf(mx, __shfl_xor_sync(0xffffffffu, mx, o));
        float e0 = __expf(v0 - mx), e1 = __expf(v1 - mx);
        float s = e0 + e1;
        for (int o = 16; o; o >>= 1) s += __shfl_xor_sync(0xffffffffu, s, o);
        float inv = 1.f / s;
        S[i][lane] = e0 * inv;
        S[i][lane + 32] = e1 * inv;
    }
    __syncthreads();

    {
        int i = tid >> 3, d = tid & 7;
        float a = 0.f;
#pragma unroll
        for (int j = 0; j < 64; j++) a = fmaf(S[i][j], Vs[j][d], a);
        int hw = (rh * 4 + (i >> 2)) * 28 + rw * 4 + (i & 3);
        ao[((size_t)b * 784 + hw) * 64 + m * 8 + d] = a;
    }
}

// ---------------- LePE: 3x3 depthwise conv on v, added into ao --------------
__global__ void bf_lepe_kernel(const float* __restrict__ qkvt, const float* __restrict__ w,
                               const float* __restrict__ bias, float* __restrict__ ao) {
    int e = blockIdx.x * blockDim.x + threadIdx.x;
    if (e >= NB * 784 * 64) return;
    int c  = e & 63;
    int hw = (e >> 6) % 784;
    int b  = e / (784 * 64);
    int h = hw / 28, wq = hw % 28;
    float acc = bias[c];
#pragma unroll
    for (int i = 0; i < 3; i++) {
        int hh = h + i - 1;
        if (hh < 0 || hh >= 28) continue;
#pragma unroll
        for (int j = 0; j < 3; j++) {
            int ww = wq + j - 1;
            if (ww < 0 || ww >= 28) continue;
            acc = fmaf(qkvt[((size_t)b * 784 + hh * 28 + ww) * 192 + 128 + c],
                       w[c * 9 + i * 3 + j], acc);
        }
    }
    ao[((size_t)b * 784 + hw) * 64 + c] += acc;
}

// ============================================================================
extern "C" void kernel_launch(void* const* d_in, const int* in_sizes, int n_in,
                              void* d_out, int out_size) {
    const float* x        = (const float*)d_in[0];
    const float* n1g      = (const float*)d_in[1];
    const float* n1b      = (const float*)d_in[2];
    const float* qkv_w    = (const float*)d_in[3];
    const float* proj_w   = (const float*)d_in[4];
    const float* proj_b   = (const float*)d_in[5];
    const float* n2g      = (const float*)d_in[6];
    const float* n2b      = (const float*)d_in[7];
    const float* fc1_w    = (const float*)d_in[8];
    const float* fc1_b    = (const float*)d_in[9];
    const float* fc2_w    = (const float*)d_in[10];
    const float* fc2_b    = (const float*)d_in[11];
    const float* bfqkv_w  = (const float*)d_in[12];
    const float* bfqkv_b  = (const float*)d_in[13];
    const float* bflepe_w = (const float*)d_in[14];
    const float* bflepe_b = (const float*)d_in[15];
    const float* bfout_w  = (const float*)d_in[16];
    const float* bfout_b  = (const float*)d_in[17];
    float* out = (float*)d_out;

    float *p_h, *p_qkv, *p_aomain, *p_o, *p_xr, *p_h2, *p_mid;
    float *p_xT, *p_bfqkv, *p_bfao, *p_bf2, *p_wqkvT, *p_woutT, *p_qr, *p_kr, *p_ar;
    int* p_idx;
    cudaGetSymbolAddress((void**)&p_h,      g_h);
    cudaGetSymbolAddress((void**)&p_qkv,    g_qkv);
    cudaGetSymbolAddress((void**)&p_aomain, g_aomain);
    cudaGetSymbolAddress((void**)&p_o,      g_o);
    cudaGetSymbolAddress((void**)&p_xr,     g_xr);
    cudaGetSymbolAddress((void**)&p_h2,     g_h2);
    cudaGetSymbolAddress((void**)&p_mid,    g_mid);
    cudaGetSymbolAddress((void**)&p_xT,     g_xT);
    cudaGetSymbolAddress((void**)&p_bfqkv,  g_bfqkv);
    cudaGetSymbolAddress((void**)&p_bfao,   g_bfao);
    cudaGetSymbolAddress((void**)&p_bf2,    g_bf2);
    cudaGetSymbolAddress((void**)&p_wqkvT,  g_wqkvT);
    cudaGetSymbolAddress((void**)&p_woutT,  g_woutT);
    cudaGetSymbolAddress((void**)&p_qr,     g_qr);
    cudaGetSymbolAddress((void**)&p_kr,     g_kr);
    cudaGetSymbolAddress((void**)&p_ar,     g_ar);
    cudaGetSymbolAddress((void**)&p_idx,    g_topk);

    cudaFuncSetAttribute(attn_kernel, cudaFuncAttributeMaxDynamicSharedMemorySize, ATTN_SMEM);

    // ---- main path up through proj ----
    ln_kernel<<<NROW, 256>>>(x, n1g, n1b, p_h);
    sgemm_kernel<<<dim3(19, 64), 256>>>(p_h, qkv_w, nullptr, nullptr, p_qkv,
                                        NROW, 3 * CDIM, CDIM, 0);
    attn_kernel<<<NB * NHD, 256, ATTN_SMEM>>>(p_qkv, p_aomain);
    sgemm_kernel<<<dim3(7, 64), 256>>>(p_aomain, proj_w, proj_b, nullptr, p_o,
                                       NROW, CDIM, CDIM, 0);

    // ---- BiFormer branch (input = o viewed as (B,64,28,28)) ----
    transpose_kernel<<<dim3(25, 2, NB), dim3(32, 32)>>>(p_o, p_xT, 64, 784);
    wtrans_kernel<<<(192 * 64 + 255) / 256, 256>>>(bfqkv_w, p_wqkvT, 192, 64);
    wtrans_kernel<<<(64 * 64 + 255) / 256, 256>>>(bfout_w, p_woutT, 64, 64);
    sgemm_kernel<<<dim3(2, M2 / 128), 256>>>(p_xT, p_wqkvT, bfqkv_b, nullptr, p_bfqkv,
                                             M2, 192, 64, 0);
    bf_pool_kernel<<<NB * 49, 128>>>(p_bfqkv, p_qr, p_kr);
    bf_ar_kernel<<<(NB * 49 * 49 + 255) / 256, 256>>>(p_qr, p_kr, p_ar);
    bf_topk_kernel<<<(NB * 49 + 255) / 256, 256>>>(p_ar, p_idx);
    bf_attn_kernel<<<NB * 8 * 49, 128>>>(p_bfqkv, p_idx, p_bfao);
    bf_lepe_kernel<<<(NB * 784 * 64 + 255) / 256, 256>>>(p_bfqkv, bflepe_w, bflepe_b, p_bfao);
    sgemm_kernel<<<dim3(1, M2 / 128), 256>>>(p_bfao, p_woutT, bfout_b, nullptr, p_bf2,
                                             M2, 64, 64, 0);
    transpose_kernel<<<dim3(2, 25, NB), dim3(32, 32)>>>(p_bf2, out + OUT1, 784, 64);

    // ---- main path: residual + LN2 + MLP ----
    add_kernel<<<(OUT1 + 255) / 256, 256>>>(p_o, x, p_xr, OUT1);
    ln_kernel<<<NROW, 256>>>(p_xr, n2g, n2b, p_h2);
    sgemm_kernel<<<dim3(25, 64), 256>>>(p_h2, fc1_w, fc1_b, nullptr, p_mid,
                                        NROW, HID, CDIM, 1);
    sgemm_kernel<<<dim3(7, 64), 256>>>(p_mid, fc2_w, fc2_b, p_xr, out,
                                       NROW, CDIM, HID, 0);
}

// round 3
// speedup vs baseline: 1.7919x; 1.7919x over previous
#include <cuda_runtime.h>
#include <math.h>

#define NB    128
#define NTOKN 64
#define CDIM  784
#define NHD   8
#define HD    98
#define HID   3136
#define NROW  (NB*NTOKN)      // 8192
#define M2    (NB*784)        // 100352
#define OUT1  (NROW*CDIM)     // 6422528

// ---------------- scratch (device globals; no allocation allowed) ----------
__device__ float g_h     [NROW*CDIM];
__device__ float g_qkv   [NROW*3*CDIM];
__device__ float g_aomain[NROW*CDIM];
__device__ float g_o     [NROW*CDIM];
__device__ float g_xr    [NROW*CDIM];
__device__ float g_h2    [NROW*CDIM];
__device__ float g_mid   [NROW*HID];
__device__ float g_xT    [M2*64];
__device__ float g_bfqkv [M2*192];
__device__ float g_bfao  [M2*64];
__device__ float g_bf2   [M2*64];
__device__ float g_wqkvT [64*192];
__device__ float g_woutT [64*64];
__device__ float g_qr    [NB*49*64];
__device__ float g_kr    [NB*49*64];
__device__ float g_ar    [NB*49*49];
__device__ int   g_topk  [NB*49*4];

// ---------------- helpers ----------------------------------------------------
__device__ __forceinline__ float f2tf32f(float x) {
    unsigned r;
    asm("cvt.rna.tf32.f32 %0, %1;" : "=r"(r) : "f"(x));
    return __uint_as_float(r);
}

__device__ __forceinline__ void mma_tf32(float& d0, float& d1, float& d2, float& d3,
                                         unsigned a0, unsigned a1, unsigned a2, unsigned a3,
                                         unsigned b0, unsigned b1) {
    asm volatile(
        "mma.sync.aligned.m16n8k8.row.col.f32.tf32.tf32.f32 "
        "{%0,%1,%2,%3}, {%4,%5,%6,%7}, {%8,%9}, {%0,%1,%2,%3};\n"
        : "+f"(d0), "+f"(d1), "+f"(d2), "+f"(d3)
        : "r"(a0), "r"(a1), "r"(a2), "r"(a3), "r"(b0), "r"(b1));
}

// ---------------- LayerNorm: one block per row -----------------------------
__global__ void ln_kernel(const float* __restrict__ x, const float* __restrict__ g,
                          const float* __restrict__ b, float* __restrict__ y) {
    int row = blockIdx.x;
    const float* xr = x + (size_t)row * CDIM;
    float* yr = y + (size_t)row * CDIM;
    float s = 0.f, s2 = 0.f;
    for (int i = threadIdx.x; i < CDIM; i += blockDim.x) {
        float v = xr[i]; s += v; s2 += v * v;
    }
    for (int o = 16; o; o >>= 1) {
        s  += __shfl_xor_sync(0xffffffffu, s,  o);
        s2 += __shfl_xor_sync(0xffffffffu, s2, o);
    }
    __shared__ float sh[16], sh2[16];
    int warp = threadIdx.x >> 5, lane = threadIdx.x & 31;
    if (lane == 0) { sh[warp] = s; sh2[warp] = s2; }
    __syncthreads();
    if (threadIdx.x == 0) {
        float t = 0.f, t2 = 0.f;
        int nw = blockDim.x >> 5;
        for (int i = 0; i < nw; i++) { t += sh[i]; t2 += sh2[i]; }
        sh[0] = t; sh2[0] = t2;
    }
    __syncthreads();
    float mean = sh[0] * (1.0f / CDIM);
    float var  = sh2[0] * (1.0f / CDIM) - mean * mean;
    float rinv = rsqrtf(var + 1e-5f);
    for (int i = threadIdx.x; i < CDIM; i += blockDim.x)
        yr[i] = (xr[i] - mean) * rinv * g[i] + b[i];
}

#define BM 128
#define BN 128
#define BK 16
#define ASTRIDE 20
#define BSTRIDE 136

// ---------------- 1xTF32 tensor-core GEMM (fast, ~1e-4) ---------------------
__global__ void __launch_bounds__(256, 2)
gemm_tf32(const float* __restrict__ A, const float* __restrict__ B,
          const float* __restrict__ bias, const float* __restrict__ res,
          float* __restrict__ C, float* __restrict__ C2, const float* __restrict__ res2,
          int M, int N, int K, int act) {
    __shared__ float As[2][BM][ASTRIDE];
    __shared__ float Bs[2][BK][BSTRIDE];

    int tid  = threadIdx.x;
    int warp = tid >> 5, lane = tid & 31;
    int wm = warp & 1, wn = warp >> 1;
    int row0 = blockIdx.y * BM, col0 = blockIdx.x * BN;

    int aRow = tid >> 2;
    int aCol = (tid & 3) * 4;
    int bRow = tid >> 4;
    int bCol = (tid & 15) * 4;

    const float* Ap0 = A + (size_t)(row0 + aRow) * K + aCol;
    const float* Ap1 = A + (size_t)(row0 + aRow + 64) * K + aCol;
    const float* Bp  = B + (size_t)bRow * N + col0 + bCol;
    bool bv0 = (col0 + bCol)      < N;
    bool bv1 = (col0 + bCol + 64) < N;

    float acc[4][4][4];
#pragma unroll
    for (int i = 0; i < 4; i++)
#pragma unroll
        for (int j = 0; j < 4; j++)
#pragma unroll
            for (int q = 0; q < 4; q++) acc[i][j][q] = 0.f;

    float4 ra0, ra1, rb0, rb1;
    const float4 z4 = make_float4(0.f, 0.f, 0.f, 0.f);

    ra0 = *(const float4*)Ap0;
    ra1 = *(const float4*)Ap1;
    rb0 = bv0 ? *(const float4*)Bp : z4;
    rb1 = bv1 ? *(const float4*)(Bp + 64) : z4;

    int nk = K / BK;
    int cur = 0;

    {
        float* a0p = &As[0][aRow][aCol];
        a0p[0] = f2tf32f(ra0.x); a0p[1] = f2tf32f(ra0.y);
        a0p[2] = f2tf32f(ra0.z); a0p[3] = f2tf32f(ra0.w);
        float* a1p = &As[0][aRow + 64][aCol];
        a1p[0] = f2tf32f(ra1.x); a1p[1] = f2tf32f(ra1.y);
        a1p[2] = f2tf32f(ra1.z); a1p[3] = f2tf32f(ra1.w);
        float* b0p = &Bs[0][bRow][bCol];
        b0p[0] = f2tf32f(rb0.x); b0p[1] = f2tf32f(rb0.y);
        b0p[2] = f2tf32f(rb0.z); b0p[3] = f2tf32f(rb0.w);
        float* b1p = &Bs[0][bRow][bCol + 64];
        b1p[0] = f2tf32f(rb1.x); b1p[1] = f2tf32f(rb1.y);
        b1p[2] = f2tf32f(rb1.z); b1p[3] = f2tf32f(rb1.w);
    }
    __syncthreads();

    int r = lane >> 2, c = lane & 3;

    for (int kt = 0; kt < nk; kt++) {
        bool more = (kt + 1) < nk;
        if (more) {
            Ap0 += BK; Ap1 += BK; Bp += (size_t)BK * N;
            ra0 = *(const float4*)Ap0;
            ra1 = *(const float4*)Ap1;
            rb0 = bv0 ? *(const float4*)Bp : z4;
            rb1 = bv1 ? *(const float4*)(Bp + 64) : z4;
        }

#pragma unroll
        for (int ks = 0; ks < 2; ks++) {
            int kk = ks * 8;
            unsigned af[4][4], bf[4][2];
#pragma unroll
            for (int mt = 0; mt < 4; mt++) {
                int m = wm * 64 + mt * 16;
                af[mt][0] = __float_as_uint(As[cur][m + r][kk + c]);
                af[mt][1] = __float_as_uint(As[cur][m + r + 8][kk + c]);
                af[mt][2] = __float_as_uint(As[cur][m + r][kk + c + 4]);
                af[mt][3] = __float_as_uint(As[cur][m + r + 8][kk + c + 4]);
            }
#pragma unroll
            for (int nt = 0; nt < 4; nt++) {
                int n = wn * 32 + nt * 8 + r;
                bf[nt][0] = __float_as_uint(Bs[cur][kk + c][n]);
                bf[nt][1] = __float_as_uint(Bs[cur][kk + c + 4][n]);
            }
#pragma unroll
            for (int mt = 0; mt < 4; mt++)
#pragma unroll
                for (int nt = 0; nt < 4; nt++)
                    mma_tf32(acc[mt][nt][0], acc[mt][nt][1], acc[mt][nt][2], acc[mt][nt][3],
                             af[mt][0], af[mt][1], af[mt][2], af[mt][3],
                             bf[nt][0], bf[nt][1]);
        }

        if (more) {
            int nxt = cur ^ 1;
            float* a0p = &As[nxt][aRow][aCol];
            a0p[0] = f2tf32f(ra0.x); a0p[1] = f2tf32f(ra0.y);
            a0p[2] = f2tf32f(ra0.z); a0p[3] = f2tf32f(ra0.w);
            float* a1p = &As[nxt][aRow + 64][aCol];
            a1p[0] = f2tf32f(ra1.x); a1p[1] = f2tf32f(ra1.y);
            a1p[2] = f2tf32f(ra1.z); a1p[3] = f2tf32f(ra1.w);
            float* b0p = &Bs[nxt][bRow][bCol];
            b0p[0] = f2tf32f(rb0.x); b0p[1] = f2tf32f(rb0.y);
            b0p[2] = f2tf32f(rb0.z); b0p[3] = f2tf32f(rb0.w);
            float* b1p = &Bs[nxt][bRow][bCol + 64];
            b1p[0] = f2tf32f(rb1.x); b1p[1] = f2tf32f(rb1.y);
            b1p[2] = f2tf32f(rb1.z); b1p[3] = f2tf32f(rb1.w);
            __syncthreads();
            cur = nxt;
        }
    }

#pragma unroll
    for (int mt = 0; mt < 4; mt++) {
        int rr0 = row0 + wm * 64 + mt * 16 + r;
#pragma unroll
        for (int nt = 0; nt < 4; nt++) {
            int cb = col0 + wn * 32 + nt * 8 + 2 * c;
#pragma unroll
            for (int half = 0; half < 2; half++) {
                int rr = rr0 + half * 8;
                float v0 = acc[mt][nt][half * 2 + 0];
                float v1 = acc[mt][nt][half * 2 + 1];
                if (bias) { if (cb < N) v0 += bias[cb]; if (cb + 1 < N) v1 += bias[cb + 1]; }
                if (act == 1) {
                    v0 = 0.5f * v0 * (1.f + erff(v0 * 0.70710678118654752f));
                    v1 = 0.5f * v1 * (1.f + erff(v1 * 0.70710678118654752f));
                }
                size_t base = (size_t)rr * N + cb;
                float w0 = v0, w1 = v1;
                if (res) { if (cb < N) w0 += res[base]; if (cb + 1 < N) w1 += res[base + 1]; }
                if (cb < N)     C[base]     = w0;
                if (cb + 1 < N) C[base + 1] = w1;
                if (C2) {
                    float u0 = v0, u1 = v1;
                    if (res2) { if (cb < N) u0 += res2[base]; if (cb + 1 < N) u1 += res2[base + 1]; }
                    if (cb < N)     C2[base]     = u0;
                    if (cb + 1 < N) C2[base + 1] = u1;
                }
            }
        }
    }
}

// ---------------- 3xTF32 error-compensated GEMM (~fp32 accuracy) ------------
// Same tiling; operands split into hi+lo tf32; acc += ah*bl + al*bh + ah*bh.
__global__ void __launch_bounds__(256, 2)
gemm_tf32x3(const float* __restrict__ A, const float* __restrict__ B,
            const float* __restrict__ bias, const float* __restrict__ res,
            float* __restrict__ C, float* __restrict__ C2, const float* __restrict__ res2,
            int M, int N, int K, int act) {
    __shared__ float Ah[BM][ASTRIDE], Al[BM][ASTRIDE];
    __shared__ float Bh[BK][BSTRIDE], Bl[BK][BSTRIDE];

    int tid  = threadIdx.x;
    int warp = tid >> 5, lane = tid & 31;
    int wm = warp & 1, wn = warp >> 1;
    int row0 = blockIdx.y * BM, col0 = blockIdx.x * BN;

    int aRow = tid >> 2;
    int aCol = (tid & 3) * 4;
    int bRow = tid >> 4;
    int bCol = (tid & 15) * 4;

    const float* Ap0 = A + (size_t)(row0 + aRow) * K + aCol;
    const float* Ap1 = A + (size_t)(row0 + aRow + 64) * K + aCol;
    const float* Bp  = B + (size_t)bRow * N + col0 + bCol;
    bool bv0 = (col0 + bCol)      < N;
    bool bv1 = (col0 + bCol + 64) < N;

    float acc[4][4][4];
#pragma unroll
    for (int i = 0; i < 4; i++)
#pragma unroll
        for (int j = 0; j < 4; j++)
#pragma unroll
            for (int q = 0; q < 4; q++) acc[i][j][q] = 0.f;

    const float4 z4 = make_float4(0.f, 0.f, 0.f, 0.f);
    int r = lane >> 2, c = lane & 3;

    for (int k0 = 0; k0 < K; k0 += BK) {
        float4 ra0 = *(const float4*)Ap0;
        float4 ra1 = *(const float4*)Ap1;
        float4 rb0 = bv0 ? *(const float4*)Bp : z4;
        float4 rb1 = bv1 ? *(const float4*)(Bp + 64) : z4;
        Ap0 += BK; Ap1 += BK; Bp += (size_t)BK * N;

        __syncthreads();
        {
            float h;
            float* ahp = &Ah[aRow][aCol]; float* alp = &Al[aRow][aCol];
            h = f2tf32f(ra0.x); ahp[0] = h; alp[0] = f2tf32f(ra0.x - h);
            h = f2tf32f(ra0.y); ahp[1] = h; alp[1] = f2tf32f(ra0.y - h);
            h = f2tf32f(ra0.z); ahp[2] = h; alp[2] = f2tf32f(ra0.z - h);
            h = f2tf32f(ra0.w); ahp[3] = h; alp[3] = f2tf32f(ra0.w - h);
            float* ahq = &Ah[aRow + 64][aCol]; float* alq = &Al[aRow + 64][aCol];
            h = f2tf32f(ra1.x); ahq[0] = h; alq[0] = f2tf32f(ra1.x - h);
            h = f2tf32f(ra1.y); ahq[1] = h; alq[1] = f2tf32f(ra1.y - h);
            h = f2tf32f(ra1.z); ahq[2] = h; alq[2] = f2tf32f(ra1.z - h);
            h = f2tf32f(ra1.w); ahq[3] = h; alq[3] = f2tf32f(ra1.w - h);
            float* bhp = &Bh[bRow][bCol]; float* blp = &Bl[bRow][bCol];
            h = f2tf32f(rb0.x); bhp[0] = h; blp[0] = f2tf32f(rb0.x - h);
            h = f2tf32f(rb0.y); bhp[1] = h; blp[1] = f2tf32f(rb0.y - h);
            h = f2tf32f(rb0.z); bhp[2] = h; blp[2] = f2tf32f(rb0.z - h);
            h = f2tf32f(rb0.w); bhp[3] = h; blp[3] = f2tf32f(rb0.w - h);
            float* bhq = &Bh[bRow][bCol + 64]; float* blq = &Bl[bRow][bCol + 64];
            h = f2tf32f(rb1.x); bhq[0] = h; blq[0] = f2tf32f(rb1.x - h);
            h = f2tf32f(rb1.y); bhq[1] = h; blq[1] = f2tf32f(rb1.y - h);
            h = f2tf32f(rb1.z); bhq[2] = h; blq[2] = f2tf32f(rb1.z - h);
            h = f2tf32f(rb1.w); bhq[3] = h; blq[3] = f2tf32f(rb1.w - h);
        }
        __syncthreads();

#pragma unroll
        for (int ks = 0; ks < 2; ks++) {
            int kk = ks * 8;
            unsigned afh[4][4], afl[4][4], bfh[4][2], bfl[4][2];
#pragma unroll
            for (int mt = 0; mt < 4; mt++) {
                int m = wm * 64 + mt * 16;
                afh[mt][0] = __float_as_uint(Ah[m + r][kk + c]);
                afh[mt][1] = __float_as_uint(Ah[m + r + 8][kk + c]);
                afh[mt][2] = __float_as_uint(Ah[m + r][kk + c + 4]);
                afh[mt][3] = __float_as_uint(Ah[m + r + 8][kk + c + 4]);
                afl[mt][0] = __float_as_uint(Al[m + r][kk + c]);
                afl[mt][1] = __float_as_uint(Al[m + r + 8][kk + c]);
                afl[mt][2] = __float_as_uint(Al[m + r][kk + c + 4]);
                afl[mt][3] = __float_as_uint(Al[m + r + 8][kk + c + 4]);
            }
#pragma unroll
            for (int nt = 0; nt < 4; nt++) {
                int n = wn * 32 + nt * 8 + r;
                bfh[nt][0] = __float_as_uint(Bh[kk + c][n]);
                bfh[nt][1] = __float_as_uint(Bh[kk + c + 4][n]);
                bfl[nt][0] = __float_as_uint(Bl[kk + c][n]);
                bfl[nt][1] = __float_as_uint(Bl[kk + c + 4][n]);
            }
#pragma unroll
            for (int mt = 0; mt < 4; mt++)
#pragma unroll
                for (int nt = 0; nt < 4; nt++) {
                    mma_tf32(acc[mt][nt][0], acc[mt][nt][1], acc[mt][nt][2], acc[mt][nt][3],
                             afh[mt][0], afh[mt][1], afh[mt][2], afh[mt][3],
                             bfl[nt][0], bfl[nt][1]);
                    mma_tf32(acc[mt][nt][0], acc[mt][nt][1], acc[mt][nt][2], acc[mt][nt][3],
                             afl[mt][0], afl[mt][1], afl[mt][2], afl[mt][3],
                             bfh[nt][0], bfh[nt][1]);
                    mma_tf32(acc[mt][nt][0], acc[mt][nt][1], acc[mt][nt][2], acc[mt][nt][3],
                             afh[mt][0], afh[mt][1], afh[mt][2], afh[mt][3],
                             bfh[nt][0], bfh[nt][1]);
                }
        }
    }

#pragma unroll
    for (int mt = 0; mt < 4; mt++) {
        int rr0 = row0 + wm * 64 + mt * 16 + r;
#pragma unroll
        for (int nt = 0; nt < 4; nt++) {
            int cb = col0 + wn * 32 + nt * 8 + 2 * c;
#pragma unroll
            for (int half = 0; half < 2; half++) {
                int rr = rr0 + half * 8;
                float v0 = acc[mt][nt][half * 2 + 0];
                float v1 = acc[mt][nt][half * 2 + 1];
                if (bias) { if (cb < N) v0 += bias[cb]; if (cb + 1 < N) v1 += bias[cb + 1]; }
                if (act == 1) {
                    v0 = 0.5f * v0 * (1.f + erff(v0 * 0.70710678118654752f));
                    v1 = 0.5f * v1 * (1.f + erff(v1 * 0.70710678118654752f));
                }
                size_t base = (size_t)rr * N + cb;
                float w0 = v0, w1 = v1;
                if (res) { if (cb < N) w0 += res[base]; if (cb + 1 < N) w1 += res[base + 1]; }
                if (cb < N)     C[base]     = w0;
                if (cb + 1 < N) C[base + 1] = w1;
                if (C2) {
                    float u0 = v0, u1 = v1;
                    if (res2) { if (cb < N) u0 += res2[base]; if (cb + 1 < N) u1 += res2[base + 1]; }
                    if (cb < N)     C2[base]     = u0;
                    if (cb + 1 < N) C2[base + 1] = u1;
                }
            }
        }
    }
}

// ---------------- fused main MHA: one block per (b, h) ---------------------
#define ATTN_SMEM ((3*64*99 + 64*64) * 4)
__global__ void attn_kernel(const float* __restrict__ qkv, float* __restrict__ out) {
    extern __shared__ float sm[];
    float* Qs = sm;
    float* Ks = Qs + 64 * 99;
    float* Vs = Ks + 64 * 99;
    float* Ss = Vs + 64 * 99;
    int b = blockIdx.x >> 3;
    int h = blockIdx.x & 7;
    const float* base = qkv + (size_t)b * 64 * (3 * CDIM) + h * HD;

    for (int e = threadIdx.x; e < 64 * HD; e += blockDim.x) {
        int r = e / HD, d = e % HD;
        const float* rp = base + (size_t)r * (3 * CDIM) + d;
        Qs[r * 99 + d] = rp[0];
        Ks[r * 99 + d] = rp[CDIM];
        Vs[r * 99 + d] = rp[2 * CDIM];
    }
    __syncthreads();

    const float scale = 1.0f / sqrtf(98.0f);
    for (int e = threadIdx.x; e < 4096; e += blockDim.x) {
        int i = e >> 6, j = e & 63;
        const float* qi = Qs + i * 99;
        const float* kj = Ks + j * 99;
        float a = 0.f;
#pragma unroll
        for (int d = 0; d < HD; d++) a = fmaf(qi[d], kj[d], a);
        Ss[e] = a * scale;
    }
    __syncthreads();

    int warp = threadIdx.x >> 5, lane = threadIdx.x & 31;
    for (int i = warp; i < 64; i += 8) {
        float v0 = Ss[i * 64 + lane], v1 = Ss[i * 64 + lane + 32];
        float mx = fmaxf(v0, v1);
        for (int o = 16; o; o >>= 1) mx = fmaxf(mx, __shfl_xor_sync(0xffffffffu, mx, o));
        float e0 = __expf(v0 - mx), e1 = __expf(v1 - mx);
        float s = e0 + e1;
        for (int o = 16; o; o >>= 1) s += __shfl_xor_sync(0xffffffffu, s, o);
        float inv = 1.f / s;
        Ss[i * 64 + lane]      = e0 * inv;
        Ss[i * 64 + lane + 32] = e1 * inv;
    }
    __syncthreads();

    for (int e = threadIdx.x; e < 64 * HD; e += blockDim.x) {
        int i = e / HD, d = e % HD;
        const float* p = Ss + i * 64;
        float a = 0.f;
#pragma unroll
        for (int j = 0; j < 64; j++) a = fmaf(p[j], Vs[j * 99 + d], a);
        out[((size_t)b * 64 + i) * CDIM + h * HD + d] = a;
    }
}

// ---------------- per-batch tiled transpose: [bt][R][Cc] -> [bt][Cc][R] -----
__global__ void transpose_kernel(const float* __restrict__ in, float* __restrict__ out,
                                 int R, int Cc) {
    __shared__ float tile[32][33];
    int b = blockIdx.z;
    int r0 = blockIdx.y * 32, c0 = blockIdx.x * 32;
    const float* ib = in + (size_t)b * R * Cc;
    float* ob = out + (size_t)b * R * Cc;
    int r = r0 + threadIdx.y, c = c0 + threadIdx.x;
    if (r < R && c < Cc) tile[threadIdx.y][threadIdx.x] = ib[(size_t)r * Cc + c];
    __syncthreads();
    int rr = r0 + threadIdx.x, cc = c0 + threadIdx.y;
    if (rr < R && cc < Cc) ob[(size_t)cc * R + rr] = tile[threadIdx.x][threadIdx.y];
}

// ---------------- small weight transpose: w[O][Cn] -> wt[Cn][O] -------------
__global__ void wtrans_kernel(const float* __restrict__ w, float* __restrict__ wt,
                              int O, int Cn) {
    int e = blockIdx.x * blockDim.x + threadIdx.x;
    if (e < O * Cn) { int o = e / Cn, c = e % Cn; wt[c * O + o] = w[e]; }
}

// ---------------- BiFormer: region mean-pool of q/k -------------------------
__global__ void bf_pool_kernel(const float* __restrict__ qkvt,
                               float* __restrict__ qr, float* __restrict__ kr) {
    int br = blockIdx.x;            // b*49 + r
    int b = br / 49, r = br % 49;
    int rh = r / 7, rw = r % 7;
    int tid = threadIdx.x;          // 128
    int c = tid & 63;
    int off = (tid >= 64) ? 64 : 0;
    int hw0 = (rh * 4) * 28 + rw * 4;
    float s = 0.f;
#pragma unroll
    for (int p = 0; p < 4; p++)
#pragma unroll
        for (int q = 0; q < 4; q++) {
            int hw = hw0 + p * 28 + q;
            s += qkvt[((size_t)b * 784 + hw) * 192 + off + c];
        }
    float* dst = (tid >= 64) ? kr : qr;
    dst[((size_t)b * 49 + r) * 64 + c] = s * (1.0f / 16.0f);
}

// ---------------- region affinity a_r[b][r][s] -------------------------------
__global__ void bf_ar_kernel(const float* __restrict__ qr, const float* __restrict__ kr,
                             float* __restrict__ ar) {
    int idx = blockIdx.x * blockDim.x + threadIdx.x;
    if (idx >= NB * 49 * 49) return;
    int s = idx % 49, r = (idx / 49) % 49, b = idx / (49 * 49);
    const float* qp = qr + ((size_t)b * 49 + r) * 64;
    const float* kp = kr + ((size_t)b * 49 + s) * 64;
    float a = 0.f;
#pragma unroll
    for (int c = 0; c < 64; c++) a = fmaf(qp[c], kp[c], a);
    ar[idx] = a;
}

// ---------------- top-4 per (b, r) -------------------------------------------
__global__ void bf_topk_kernel(const float* __restrict__ ar, int* __restrict__ idx) {
    int t = blockIdx.x * blockDim.x + threadIdx.x;
    if (t >= NB * 49) return;
    float v[49];
    const float* row = ar + (size_t)t * 49;
#pragma unroll
    for (int s = 0; s < 49; s++) v[s] = row[s];
    for (int k = 0; k < 4; k++) {
        float best = -3.4e38f; int bi = 0;
        for (int s = 0; s < 49; s++)
            if (v[s] > best) { best = v[s]; bi = s; }
        idx[t * 4 + k] = bi;
        v[bi] = -3.4e38f;
    }
}

// ---------------- BiFormer region attention: one block per (b, m, r) ---------
__global__ void bf_attn_kernel(const float* __restrict__ qkvt, const int* __restrict__ idx,
                               float* __restrict__ ao) {
    __shared__ float Qs[16][8], Ks[64][9], Vs[64][9], S[16][64];
    __shared__ int sreg[4];
    int r = blockIdx.x % 49;
    int m = (blockIdx.x / 49) & 7;
    int b = blockIdx.x / (49 * 8);
    int tid = threadIdx.x;                 // 128
    int rh = r / 7, rw = r % 7;

    if (tid < 4) sreg[tid] = idx[((size_t)b * 49 + r) * 4 + tid];
    {
        int p = tid >> 3, d = tid & 7;
        int hw = (rh * 4 + (p >> 2)) * 28 + rw * 4 + (p & 3);
        Qs[p][d] = qkvt[((size_t)b * 784 + hw) * 192 + m * 8 + d];
    }
    __syncthreads();

    for (int e = tid; e < 512; e += 128) {
        int slot = e >> 3, d = e & 7;
        int t = slot >> 4, s = slot & 15;
        int sr = sreg[t];
        int hw = ((sr / 7) * 4 + (s >> 2)) * 28 + (sr % 7) * 4 + (s & 3);
        const float* p = qkvt + ((size_t)b * 784 + hw) * 192 + m * 8 + d;
        Ks[slot][d] = p[64];
        Vs[slot][d] = p[128];
    }
    __syncthreads();

    for (int e = tid; e < 1024; e += 128) {
        int i = e >> 6, j = e & 63;
        float a = 0.f;
#pragma unroll
        for (int d = 0; d < 8; d++) a = fmaf(Qs[i][d], Ks[j][d], a);
        S[i][j] = a * 0.125f;
    }
    __syncthreads();

    int warp = tid >> 5, lane = tid & 31;
    for (int i = warp; i < 16; i += 4) {
        float v0 = S[i][lane], v1 = S[i][lane + 32];
        float mx = fmaxf(v0, v1);
        for (int o = 16; o; o >>= 1) mx = fmaxf(mx, __shfl_xor_sync(0xffffffffu, mx, o));
        float e0 = __expf(v0 - mx), e1 = __expf(v1 - mx);
        float s = e0 + e1;
        for (int o = 16; o; o >>= 1) s += __shfl_xor_sync(0xffffffffu, s, o);
        float inv = 1.f / s;
        S[i][lane] = e0 * inv;
        S[i][lane + 32] = e1 * inv;
    }
    __syncthreads();

    {
        int i = tid >> 3, d = tid & 7;
        float a = 0.f;
#pragma unroll
        for (int j = 0; j < 64; j++) a = fmaf(S[i][j], Vs[j][d], a);
        int hw = (rh * 4 + (i >> 2)) * 28 + rw * 4 + (i & 3);
        ao[((size_t)b * 784 + hw) * 64 + m * 8 + d] = a;
    }
}

// ---------------- LePE: 3x3 depthwise conv on v, added into ao --------------
__global__ void bf_lepe_kernel(const float* __restrict__ qkvt, const float* __restrict__ w,
                               const float* __restrict__ bias, float* __restrict__ ao) {
    int e = blockIdx.x * blockDim.x + threadIdx.x;
    if (e >= NB * 784 * 64) return;
    int c  = e & 63;
    int hw = (e >> 6) % 784;
    int b  = e / (784 * 64);
    int h = hw / 28, wq = hw % 28;
    float acc = bias[c];
#pragma unroll
    for (int i = 0; i < 3; i++) {
        int hh = h + i - 1;
        if (hh < 0 || hh >= 28) continue;
#pragma unroll
        for (int j = 0; j < 3; j++) {
            int ww = wq + j - 1;
            if (ww < 0 || ww >= 28) continue;
            acc = fmaf(qkvt[((size_t)b * 784 + hh * 28 + ww) * 192 + 128 + c],
                       w[c * 9 + i * 3 + j], acc);
        }
    }
    ao[((size_t)b * 784 + hw) * 64 + c] += acc;
}

// ============================================================================
extern "C" void kernel_launch(void* const* d_in, const int* in_sizes, int n_in,
                              void* d_out, int out_size) {
    const float* x        = (const float*)d_in[0];
    const float* n1g      = (const float*)d_in[1];
    const float* n1b      = (const float*)d_in[2];
    const float* qkv_w    = (const float*)d_in[3];
    const float* proj_w   = (const float*)d_in[4];
    const float* proj_b   = (const float*)d_in[5];
    const float* n2g      = (const float*)d_in[6];
    const float* n2b      = (const float*)d_in[7];
    const float* fc1_w    = (const float*)d_in[8];
    const float* fc1_b    = (const float*)d_in[9];
    const float* fc2_w    = (const float*)d_in[10];
    const float* fc2_b    = (const float*)d_in[11];
    const float* bfqkv_w  = (const float*)d_in[12];
    const float* bfqkv_b  = (const float*)d_in[13];
    const float* bflepe_w = (const float*)d_in[14];
    const float* bflepe_b = (const float*)d_in[15];
    const float* bfout_w  = (const float*)d_in[16];
    const float* bfout_b  = (const float*)d_in[17];
    float* out = (float*)d_out;

    float *p_h, *p_qkv, *p_aomain, *p_o, *p_xr, *p_h2, *p_mid;
    float *p_xT, *p_bfqkv, *p_bfao, *p_bf2, *p_wqkvT, *p_woutT, *p_qr, *p_kr, *p_ar;
    int* p_idx;
    cudaGetSymbolAddress((void**)&p_h,      g_h);
    cudaGetSymbolAddress((void**)&p_qkv,    g_qkv);
    cudaGetSymbolAddress((void**)&p_aomain, g_aomain);
    cudaGetSymbolAddress((void**)&p_o,      g_o);
    cudaGetSymbolAddress((void**)&p_xr,     g_xr);
    cudaGetSymbolAddress((void**)&p_h2,     g_h2);
    cudaGetSymbolAddress((void**)&p_mid,    g_mid);
    cudaGetSymbolAddress((void**)&p_xT,     g_xT);
    cudaGetSymbolAddress((void**)&p_bfqkv,  g_bfqkv);
    cudaGetSymbolAddress((void**)&p_bfao,   g_bfao);
    cudaGetSymbolAddress((void**)&p_bf2,    g_bf2);
    cudaGetSymbolAddress((void**)&p_wqkvT,  g_wqkvT);
    cudaGetSymbolAddress((void**)&p_woutT,  g_woutT);
    cudaGetSymbolAddress((void**)&p_qr,     g_qr);
    cudaGetSymbolAddress((void**)&p_kr,     g_kr);
    cudaGetSymbolAddress((void**)&p_ar,     g_ar);
    cudaGetSymbolAddress((void**)&p_idx,    g_topk);

    cudaFuncSetAttribute(attn_kernel, cudaFuncAttributeMaxDynamicSharedMemorySize, ATTN_SMEM);

    // ---- main path up through proj (3xTF32: feeds routing-sensitive branch) ----
    ln_kernel<<<NROW, 256>>>(x, n1g, n1b, p_h);
    gemm_tf32x3<<<dim3(19, 64), 256>>>(p_h, qkv_w, nullptr, nullptr, p_qkv, nullptr, nullptr,
                                       NROW, 3 * CDIM, CDIM, 0);
    attn_kernel<<<NB * NHD, 256, ATTN_SMEM>>>(p_qkv, p_aomain);
    gemm_tf32x3<<<dim3(7, 64), 256>>>(p_aomain, proj_w, proj_b, nullptr, p_o, p_xr, x,
                                      NROW, CDIM, CDIM, 0);

    // ---- BiFormer branch (3xTF32 everywhere) ----
    transpose_kernel<<<dim3(25, 2, NB), dim3(32, 32)>>>(p_o, p_xT, 64, 784);
    wtrans_kernel<<<(192 * 64 + 255) / 256, 256>>>(bfqkv_w, p_wqkvT, 192, 64);
    wtrans_kernel<<<(64 * 64 + 255) / 256, 256>>>(bfout_w, p_woutT, 64, 64);
    gemm_tf32x3<<<dim3(2, M2 / 128), 256>>>(p_xT, p_wqkvT, bfqkv_b, nullptr, p_bfqkv,
                                            nullptr, nullptr, M2, 192, 64, 0);
    bf_pool_kernel<<<NB * 49, 128>>>(p_bfqkv, p_qr, p_kr);
    bf_ar_kernel<<<(NB * 49 * 49 + 255) / 256, 256>>>(p_qr, p_kr, p_ar);
    bf_topk_kernel<<<(NB * 49 + 255) / 256, 256>>>(p_ar, p_idx);
    bf_attn_kernel<<<NB * 8 * 49, 128>>>(p_bfqkv, p_idx, p_bfao);
    bf_lepe_kernel<<<(NB * 784 * 64 + 255) / 256, 256>>>(p_bfqkv, bflepe_w, bflepe_b, p_bfao);
    gemm_tf32x3<<<dim3(1, M2 / 128), 256>>>(p_bfao, p_woutT, bfout_b, nullptr, p_bf2,
                                            nullptr, nullptr, M2, 64, 64, 0);
    transpose_kernel<<<dim3(2, 25, NB), dim3(32, 32)>>>(p_bf2, out + OUT1, 784, 64);

    // ---- main path: LN2 + MLP (1xTF32; output0 tolerance has margin) ----
    ln_kernel<<<NROW, 256>>>(p_xr, n2g, n2b, p_h2);
    gemm_tf32<<<dim3(25, 64), 256>>>(p_h2, fc1_w, fc1_b, nullptr, p_mid, nullptr, nullptr,
                                     NROW, HID, CDIM, 1);
    gemm_tf32<<<dim3(7, 64), 256>>>(p_mid, fc2_w, fc2_b, p_xr, out, nullptr, nullptr,
                                    NROW, CDIM, HID, 0);
}

// round 4
// speedup vs baseline: 2.0802x; 1.1609x over previous
#include <cuda_runtime.h>
#include <math.h>

#define NB    128
#define NTOKN 64
#define CDIM  784
#define NHD   8
#define HD    98
#define HID   3136
#define NROW  (NB*NTOKN)      // 8192
#define M2    (NB*784)        // 100352
#define OUT1  (NROW*CDIM)     // 6422528

// ---------------- scratch (device globals; no allocation allowed) ----------
__device__ float g_h     [NROW*CDIM];
__device__ float g_qkv   [NROW*3*CDIM];
__device__ float g_aomain[NROW*CDIM];
__device__ float g_o     [NROW*CDIM];
__device__ float g_xr    [NROW*CDIM];
__device__ float g_h2    [NROW*CDIM];
__device__ float g_mid   [NROW*HID];
__device__ float g_xT    [M2*64];
__device__ float g_bfqkv [M2*192];
__device__ float g_bfao  [M2*64];
__device__ float g_bf2   [M2*64];
__device__ float g_wqkvT [64*192];
__device__ float g_woutT [64*64];
__device__ float g_qr    [NB*49*64];
__device__ float g_kr    [NB*49*64];
__device__ float g_ar    [NB*49*49];
__device__ int   g_topk  [NB*49*4];

// ---------------- helpers ----------------------------------------------------
__device__ __forceinline__ float f2tf32f(float x) {
    unsigned r;
    asm("cvt.rna.tf32.f32 %0, %1;" : "=r"(r) : "f"(x));
    return __uint_as_float(r);
}

__device__ __forceinline__ void mma_tf32(float& d0, float& d1, float& d2, float& d3,
                                         unsigned a0, unsigned a1, unsigned a2, unsigned a3,
                                         unsigned b0, unsigned b1) {
    asm volatile(
        "mma.sync.aligned.m16n8k8.row.col.f32.tf32.tf32.f32 "
        "{%0,%1,%2,%3}, {%4,%5,%6,%7}, {%8,%9}, {%0,%1,%2,%3};\n"
        : "+f"(d0), "+f"(d1), "+f"(d2), "+f"(d3)
        : "r"(a0), "r"(a1), "r"(a2), "r"(a3), "r"(b0), "r"(b1));
}

__device__ __forceinline__ void cp16(void* dst, const void* src, bool pred) {
    unsigned daddr = (unsigned)__cvta_generic_to_shared(dst);
    int sz = pred ? 16 : 0;
    asm volatile("cp.async.cg.shared.global [%0], [%1], 16, %2;\n"
                 :: "r"(daddr), "l"(src), "r"(sz));
}
#define CP_COMMIT() asm volatile("cp.async.commit_group;\n" ::: "memory")
#define CP_WAIT2()  asm volatile("cp.async.wait_group 2;\n" ::: "memory")

// ---------------- LayerNorm: one block per row -----------------------------
__global__ void ln_kernel(const float* __restrict__ x, const float* __restrict__ g,
                          const float* __restrict__ b, float* __restrict__ y) {
    int row = blockIdx.x;
    const float* xr = x + (size_t)row * CDIM;
    float* yr = y + (size_t)row * CDIM;
    float s = 0.f, s2 = 0.f;
    for (int i = threadIdx.x; i < CDIM; i += blockDim.x) {
        float v = xr[i]; s += v; s2 += v * v;
    }
    for (int o = 16; o; o >>= 1) {
        s  += __shfl_xor_sync(0xffffffffu, s,  o);
        s2 += __shfl_xor_sync(0xffffffffu, s2, o);
    }
    __shared__ float sh[16], sh2[16];
    int warp = threadIdx.x >> 5, lane = threadIdx.x & 31;
    if (lane == 0) { sh[warp] = s; sh2[warp] = s2; }
    __syncthreads();
    if (threadIdx.x == 0) {
        float t = 0.f, t2 = 0.f;
        int nw = blockDim.x >> 5;
        for (int i = 0; i < nw; i++) { t += sh[i]; t2 += sh2[i]; }
        sh[0] = t; sh2[0] = t2;
    }
    __syncthreads();
    float mean = sh[0] * (1.0f / CDIM);
    float var  = sh2[0] * (1.0f / CDIM) - mean * mean;
    float rinv = rsqrtf(var + 1e-5f);
    for (int i = threadIdx.x; i < CDIM; i += blockDim.x)
        yr[i] = (xr[i] - mean) * rinv * g[i] + b[i];
}

// ---------------- pipelined TF32 GEMM (PASSES = 1 or 3) ---------------------
// C = A(MxK) @ B(KxN) [+bias] [gelu] [+res]; optional C2 = v + res2.
// Requires M%128==0, K%16==0, N%16==0.
// 3-stage cp.async pipeline, raw f32 in smem, tf32 hi/lo split at frag load.
#define BM 128
#define BN 128
#define BK 16
#define STAGES 3
#define GSMEM ((STAGES*BM*20 + STAGES*BK*136) * 4)   // 56832 bytes

template<int PASSES>
__global__ void __launch_bounds__(256, 2)
gemm_pipe(const float* __restrict__ A, const float* __restrict__ B,
          const float* __restrict__ bias, const float* __restrict__ res,
          float* __restrict__ C, float* __restrict__ C2, const float* __restrict__ res2,
          int M, int N, int K, int act) {
    extern __shared__ float smraw[];
    float (*As)[BM][20]  = (float(*)[BM][20])smraw;
    float (*Bs)[BK][136] = (float(*)[BK][136])(smraw + STAGES * BM * 20);

    int tid  = threadIdx.x;
    int warp = tid >> 5, lane = tid & 31;
    int wm = warp & 1, wn = warp >> 1;
    int row0 = blockIdx.y * BM, col0 = blockIdx.x * BN;

    int aRow = tid >> 2, aCol = (tid & 3) * 4;
    int bRow = tid >> 5, bCol = (tid & 31) * 4;
    bool bp = (col0 + bCol) < N;

    float acc[4][4][4];
#pragma unroll
    for (int i = 0; i < 4; i++)
#pragma unroll
        for (int j = 0; j < 4; j++)
#pragma unroll
            for (int q = 0; q < 4; q++) acc[i][j][q] = 0.f;

    int nk = K / BK;

#define PREF(SIDX, K0) do { \
        cp16(&As[SIDX][aRow][aCol],      A + (size_t)(row0 + aRow) * K + (K0) + aCol, true); \
        cp16(&As[SIDX][aRow + 64][aCol], A + (size_t)(row0 + aRow + 64) * K + (K0) + aCol, true); \
        cp16(&Bs[SIDX][bRow][bCol],      B + (size_t)((K0) + bRow) * N + col0 + bCol, bp); \
        cp16(&Bs[SIDX][bRow + 8][bCol],  B + (size_t)((K0) + bRow + 8) * N + col0 + bCol, bp); \
    } while (0)

    PREF(0, 0);
    CP_COMMIT();
    if (nk > 1) PREF(1, BK);
    CP_COMMIT();

    int r = lane >> 2, c = lane & 3;

    for (int kt = 0; kt < nk; kt++) {
        int kn = kt + 2;
        if (kn < nk) { int sn = kn % STAGES; PREF(sn, kn * BK); }
        CP_COMMIT();
        CP_WAIT2();
        __syncthreads();

        int s = kt % STAGES;
#pragma unroll
        for (int ks = 0; ks < 2; ks++) {
            int kk = ks * 8;
            unsigned afh[4][4], bfh[4][2];
            unsigned afl[4][4], bfl[4][2];
#pragma unroll
            for (int mt = 0; mt < 4; mt++) {
                int m = wm * 64 + mt * 16;
                float x0 = As[s][m + r][kk + c];
                float x1 = As[s][m + r + 8][kk + c];
                float x2 = As[s][m + r][kk + c + 4];
                float x3 = As[s][m + r + 8][kk + c + 4];
                float h0 = f2tf32f(x0), h1 = f2tf32f(x1);
                float h2 = f2tf32f(x2), h3 = f2tf32f(x3);
                afh[mt][0] = __float_as_uint(h0); afh[mt][1] = __float_as_uint(h1);
                afh[mt][2] = __float_as_uint(h2); afh[mt][3] = __float_as_uint(h3);
                if (PASSES == 3) {
                    afl[mt][0] = __float_as_uint(f2tf32f(x0 - h0));
                    afl[mt][1] = __float_as_uint(f2tf32f(x1 - h1));
                    afl[mt][2] = __float_as_uint(f2tf32f(x2 - h2));
                    afl[mt][3] = __float_as_uint(f2tf32f(x3 - h3));
                }
            }
#pragma unroll
            for (int nt = 0; nt < 4; nt++) {
                int n = wn * 32 + nt * 8 + r;
                float y0 = Bs[s][kk + c][n];
                float y1 = Bs[s][kk + c + 4][n];
                float g0 = f2tf32f(y0), g1 = f2tf32f(y1);
                bfh[nt][0] = __float_as_uint(g0); bfh[nt][1] = __float_as_uint(g1);
                if (PASSES == 3) {
                    bfl[nt][0] = __float_as_uint(f2tf32f(y0 - g0));
                    bfl[nt][1] = __float_as_uint(f2tf32f(y1 - g1));
                }
            }
#pragma unroll
            for (int mt = 0; mt < 4; mt++)
#pragma unroll
                for (int nt = 0; nt < 4; nt++) {
                    if (PASSES == 3) {
                        mma_tf32(acc[mt][nt][0], acc[mt][nt][1], acc[mt][nt][2], acc[mt][nt][3],
                                 afh[mt][0], afh[mt][1], afh[mt][2], afh[mt][3],
                                 bfl[nt][0], bfl[nt][1]);
                        mma_tf32(acc[mt][nt][0], acc[mt][nt][1], acc[mt][nt][2], acc[mt][nt][3],
                                 afl[mt][0], afl[mt][1], afl[mt][2], afl[mt][3],
                                 bfh[nt][0], bfh[nt][1]);
                    }
                    mma_tf32(acc[mt][nt][0], acc[mt][nt][1], acc[mt][nt][2], acc[mt][nt][3],
                             afh[mt][0], afh[mt][1], afh[mt][2], afh[mt][3],
                             bfh[nt][0], bfh[nt][1]);
                }
        }
        __syncthreads();
    }
#undef PREF

    // epilogue
#pragma unroll
    for (int mt = 0; mt < 4; mt++) {
        int rr0 = row0 + wm * 64 + mt * 16 + r;
#pragma unroll
        for (int nt = 0; nt < 4; nt++) {
            int cb = col0 + wn * 32 + nt * 8 + 2 * c;
#pragma unroll
            for (int half = 0; half < 2; half++) {
                int rr = rr0 + half * 8;
                float v0 = acc[mt][nt][half * 2 + 0];
                float v1 = acc[mt][nt][half * 2 + 1];
                if (bias) { if (cb < N) v0 += bias[cb]; if (cb + 1 < N) v1 += bias[cb + 1]; }
                if (act == 1) {
                    v0 = 0.5f * v0 * (1.f + erff(v0 * 0.70710678118654752f));
                    v1 = 0.5f * v1 * (1.f + erff(v1 * 0.70710678118654752f));
                }
                size_t base = (size_t)rr * N + cb;
                float w0 = v0, w1 = v1;
                if (res) { if (cb < N) w0 += res[base]; if (cb + 1 < N) w1 += res[base + 1]; }
                if (cb < N)     C[base]     = w0;
                if (cb + 1 < N) C[base + 1] = w1;
                if (C2) {
                    float u0 = v0, u1 = v1;
                    if (res2) { if (cb < N) u0 += res2[base]; if (cb + 1 < N) u1 += res2[base + 1]; }
                    if (cb < N)     C2[base]     = u0;
                    if (cb + 1 < N) C2[base + 1] = u1;
                }
            }
        }
    }
}

// ---------------- fused main MHA: one block per (b, h) ---------------------
#define ATTN_SMEM ((3*64*99 + 64*64) * 4)
__global__ void attn_kernel(const float* __restrict__ qkv, float* __restrict__ out) {
    extern __shared__ float sm[];
    float* Qs = sm;
    float* Ks = Qs + 64 * 99;
    float* Vs = Ks + 64 * 99;
    float* Ss = Vs + 64 * 99;
    int b = blockIdx.x >> 3;
    int h = blockIdx.x & 7;
    const float* base = qkv + (size_t)b * 64 * (3 * CDIM) + h * HD;

    for (int e = threadIdx.x; e < 64 * HD; e += blockDim.x) {
        int r = e / HD, d = e % HD;
        const float* rp = base + (size_t)r * (3 * CDIM) + d;
        Qs[r * 99 + d] = rp[0];
        Ks[r * 99 + d] = rp[CDIM];
        Vs[r * 99 + d] = rp[2 * CDIM];
    }
    __syncthreads();

    const float scale = 1.0f / sqrtf(98.0f);
    for (int e = threadIdx.x; e < 4096; e += blockDim.x) {
        int i = e >> 6, j = e & 63;
        const float* qi = Qs + i * 99;
        const float* kj = Ks + j * 99;
        float a = 0.f;
#pragma unroll
        for (int d = 0; d < HD; d++) a = fmaf(qi[d], kj[d], a);
        Ss[e] = a * scale;
    }
    __syncthreads();

    int warp = threadIdx.x >> 5, lane = threadIdx.x & 31;
    for (int i = warp; i < 64; i += 8) {
        float v0 = Ss[i * 64 + lane], v1 = Ss[i * 64 + lane + 32];
        float mx = fmaxf(v0, v1);
        for (int o = 16; o; o >>= 1) mx = fmaxf(mx, __shfl_xor_sync(0xffffffffu, mx, o));
        float e0 = __expf(v0 - mx), e1 = __expf(v1 - mx);
        float s = e0 + e1;
        for (int o = 16; o; o >>= 1) s += __shfl_xor_sync(0xffffffffu, s, o);
        float inv = 1.f / s;
        Ss[i * 64 + lane]      = e0 * inv;
        Ss[i * 64 + lane + 32] = e1 * inv;
    }
    __syncthreads();

    for (int e = threadIdx.x; e < 64 * HD; e += blockDim.x) {
        int i = e / HD, d = e % HD;
        const float* p = Ss + i * 64;
        float a = 0.f;
#pragma unroll
        for (int j = 0; j < 64; j++) a = fmaf(p[j], Vs[j * 99 + d], a);
        out[((size_t)b * 64 + i) * CDIM + h * HD + d] = a;
    }
}

// ---------------- per-batch tiled transpose: [bt][R][Cc] -> [bt][Cc][R] -----
__global__ void transpose_kernel(const float* __restrict__ in, float* __restrict__ out,
                                 int R, int Cc) {
    __shared__ float tile[32][33];
    int b = blockIdx.z;
    int r0 = blockIdx.y * 32, c0 = blockIdx.x * 32;
    const float* ib = in + (size_t)b * R * Cc;
    float* ob = out + (size_t)b * R * Cc;
    int r = r0 + threadIdx.y, c = c0 + threadIdx.x;
    if (r < R && c < Cc) tile[threadIdx.y][threadIdx.x] = ib[(size_t)r * Cc + c];
    __syncthreads();
    int rr = r0 + threadIdx.x, cc = c0 + threadIdx.y;
    if (rr < R && cc < Cc) ob[(size_t)cc * R + rr] = tile[threadIdx.x][threadIdx.y];
}

// ---------------- small weight transpose: w[O][Cn] -> wt[Cn][O] -------------
__global__ void wtrans_kernel(const float* __restrict__ w, float* __restrict__ wt,
                              int O, int Cn) {
    int e = blockIdx.x * blockDim.x + threadIdx.x;
    if (e < O * Cn) { int o = e / Cn, c = e % Cn; wt[c * O + o] = w[e]; }
}

// ---------------- BiFormer: region mean-pool of q/k -------------------------
__global__ void bf_pool_kernel(const float* __restrict__ qkvt,
                               float* __restrict__ qr, float* __restrict__ kr) {
    int br = blockIdx.x;            // b*49 + r
    int b = br / 49, r = br % 49;
    int rh = r / 7, rw = r % 7;
    int tid = threadIdx.x;          // 128
    int c = tid & 63;
    int off = (tid >= 64) ? 64 : 0;
    int hw0 = (rh * 4) * 28 + rw * 4;
    float s = 0.f;
#pragma unroll
    for (int p = 0; p < 4; p++)
#pragma unroll
        for (int q = 0; q < 4; q++) {
            int hw = hw0 + p * 28 + q;
            s += qkvt[((size_t)b * 784 + hw) * 192 + off + c];
        }
    float* dst = (tid >= 64) ? kr : qr;
    dst[((size_t)b * 49 + r) * 64 + c] = s * (1.0f / 16.0f);
}

// ---------------- region affinity a_r[b][r][s] -------------------------------
__global__ void bf_ar_kernel(const float* __restrict__ qr, const float* __restrict__ kr,
                             float* __restrict__ ar) {
    int idx = blockIdx.x * blockDim.x + threadIdx.x;
    if (idx >= NB * 49 * 49) return;
    int s = idx % 49, r = (idx / 49) % 49, b = idx / (49 * 49);
    const float* qp = qr + ((size_t)b * 49 + r) * 64;
    const float* kp = kr + ((size_t)b * 49 + s) * 64;
    float a = 0.f;
#pragma unroll
    for (int c = 0; c < 64; c++) a = fmaf(qp[c], kp[c], a);
    ar[idx] = a;
}

// ---------------- top-4 per (b, r) -------------------------------------------
__global__ void bf_topk_kernel(const float* __restrict__ ar, int* __restrict__ idx) {
    int t = blockIdx.x * blockDim.x + threadIdx.x;
    if (t >= NB * 49) return;
    float v[49];
    const float* row = ar + (size_t)t * 49;
#pragma unroll
    for (int s = 0; s < 49; s++) v[s] = row[s];
    for (int k = 0; k < 4; k++) {
        float best = -3.4e38f; int bi = 0;
        for (int s = 0; s < 49; s++)
            if (v[s] > best) { best = v[s]; bi = s; }
        idx[t * 4 + k] = bi;
        v[bi] = -3.4e38f;
    }
}

// ---------------- BiFormer region attention: one block per (b, m, r) ---------
__global__ void bf_attn_kernel(const float* __restrict__ qkvt, const int* __restrict__ idx,
                               float* __restrict__ ao) {
    __shared__ float Qs[16][8], Ks[64][9], Vs[64][9], S[16][64];
    __shared__ int sreg[4];
    int r = blockIdx.x % 49;
    int m = (blockIdx.x / 49) & 7;
    int b = blockIdx.x / (49 * 8);
    int tid = threadIdx.x;                 // 128
    int rh = r / 7, rw = r % 7;

    if (tid < 4) sreg[tid] = idx[((size_t)b * 49 + r) * 4 + tid];
    {
        int p = tid >> 3, d = tid & 7;
        int hw = (rh * 4 + (p >> 2)) * 28 + rw * 4 + (p & 3);
        Qs[p][d] = qkvt[((size_t)b * 784 + hw) * 192 + m * 8 + d];
    }
    __syncthreads();

    for (int e = tid; e < 512; e += 128) {
        int slot = e >> 3, d = e & 7;
        int t = slot >> 4, s = slot & 15;
        int sr = sreg[t];
        int hw = ((sr / 7) * 4 + (s >> 2)) * 28 + (sr % 7) * 4 + (s & 3);
        const float* p = qkvt + ((size_t)b * 784 + hw) * 192 + m * 8 + d;
        Ks[slot][d] = p[64];
        Vs[slot][d] = p[128];
    }
    __syncthreads();

    for (int e = tid; e < 1024; e += 128) {
        int i = e >> 6, j = e & 63;
        float a = 0.f;
#pragma unroll
        for (int d = 0; d < 8; d++) a = fmaf(Qs[i][d], Ks[j][d], a);
        S[i][j] = a * 0.125f;
    }
    __syncthreads();

    int warp = tid >> 5, lane = tid & 31;
    for (int i = warp; i < 16; i += 4) {
        float v0 = S[i][lane], v1 = S[i][lane + 32];
        float mx = fmaxf(v0, v1);
        for (int o = 16; o; o >>= 1) mx = fmaxf(mx, __shfl_xor_sync(0xffffffffu, mx, o));
        float e0 = __expf(v0 - mx), e1 = __expf(v1 - mx);
        float s = e0 + e1;
        for (int o = 16; o; o >>= 1) s += __shfl_xor_sync(0xffffffffu, s, o);
        float inv = 1.f / s;
        S[i][lane] = e0 * inv;
        S[i][lane + 32] = e1 * inv;
    }
    __syncthreads();

    {
        int i = tid >> 3, d = tid & 7;
        float a = 0.f;
#pragma unroll
        for (int j = 0; j < 64; j++) a = fmaf(S[i][j], Vs[j][d], a);
        int hw = (rh * 4 + (i >> 2)) * 28 + rw * 4 + (i & 3);
        ao[((size_t)b * 784 + hw) * 64 + m * 8 + d] = a;
    }
}

// ---------------- LePE: 3x3 depthwise conv on v, added into ao --------------
__global__ void bf_lepe_kernel(const float* __restrict__ qkvt, const float* __restrict__ w,
                               const float* __restrict__ bias, float* __restrict__ ao) {
    int e = blockIdx.x * blockDim.x + threadIdx.x;
    if (e >= NB * 784 * 64) return;
    int c  = e & 63;
    int hw = (e >> 6) % 784;
    int b  = e / (784 * 64);
    int h = hw / 28, wq = hw % 28;
    float acc = bias[c];
#pragma unroll
    for (int i = 0; i < 3; i++) {
        int hh = h + i - 1;
        if (hh < 0 || hh >= 28) continue;
#pragma unroll
        for (int j = 0; j < 3; j++) {
            int ww = wq + j - 1;
            if (ww < 0 || ww >= 28) continue;
            acc = fmaf(qkvt[((size_t)b * 784 + hh * 28 + ww) * 192 + 128 + c],
                       w[c * 9 + i * 3 + j], acc);
        }
    }
    ao[((size_t)b * 784 + hw) * 64 + c] += acc;
}

// ============================================================================
extern "C" void kernel_launch(void* const* d_in, const int* in_sizes, int n_in,
                              void* d_out, int out_size) {
    const float* x        = (const float*)d_in[0];
    const float* n1g      = (const float*)d_in[1];
    const float* n1b      = (const float*)d_in[2];
    const float* qkv_w    = (const float*)d_in[3];
    const float* proj_w   = (const float*)d_in[4];
    const float* proj_b   = (const float*)d_in[5];
    const float* n2g      = (const float*)d_in[6];
    const float* n2b      = (const float*)d_in[7];
    const float* fc1_w    = (const float*)d_in[8];
    const float* fc1_b    = (const float*)d_in[9];
    const float* fc2_w    = (const float*)d_in[10];
    const float* fc2_b    = (const float*)d_in[11];
    const float* bfqkv_w  = (const float*)d_in[12];
    const float* bfqkv_b  = (const float*)d_in[13];
    const float* bflepe_w = (const float*)d_in[14];
    const float* bflepe_b = (const float*)d_in[15];
    const float* bfout_w  = (const float*)d_in[16];
    const float* bfout_b  = (const float*)d_in[17];
    float* out = (float*)d_out;

    float *p_h, *p_qkv, *p_aomain, *p_o, *p_xr, *p_h2, *p_mid;
    float *p_xT, *p_bfqkv, *p_bfao, *p_bf2, *p_wqkvT, *p_woutT, *p_qr, *p_kr, *p_ar;
    int* p_idx;
    cudaGetSymbolAddress((void**)&p_h,      g_h);
    cudaGetSymbolAddress((void**)&p_qkv,    g_qkv);
    cudaGetSymbolAddress((void**)&p_aomain, g_aomain);
    cudaGetSymbolAddress((void**)&p_o,      g_o);
    cudaGetSymbolAddress((void**)&p_xr,     g_xr);
    cudaGetSymbolAddress((void**)&p_h2,     g_h2);
    cudaGetSymbolAddress((void**)&p_mid,    g_mid);
    cudaGetSymbolAddress((void**)&p_xT,     g_xT);
    cudaGetSymbolAddress((void**)&p_bfqkv,  g_bfqkv);
    cudaGetSymbolAddress((void**)&p_bfao,   g_bfao);
    cudaGetSymbolAddress((void**)&p_bf2,    g_bf2);
    cudaGetSymbolAddress((void**)&p_wqkvT,  g_wqkvT);
    cudaGetSymbolAddress((void**)&p_woutT,  g_woutT);
    cudaGetSymbolAddress((void**)&p_qr,     g_qr);
    cudaGetSymbolAddress((void**)&p_kr,     g_kr);
    cudaGetSymbolAddress((void**)&p_ar,     g_ar);
    cudaGetSymbolAddress((void**)&p_idx,    g_topk);

    cudaFuncSetAttribute(attn_kernel, cudaFuncAttributeMaxDynamicSharedMemorySize, ATTN_SMEM);
    cudaFuncSetAttribute(gemm_pipe<1>, cudaFuncAttributeMaxDynamicSharedMemorySize, GSMEM);
    cudaFuncSetAttribute(gemm_pipe<3>, cudaFuncAttributeMaxDynamicSharedMemorySize, GSMEM);

    // ---- main path up through proj (3xTF32: feeds routing-sensitive branch) ----
    ln_kernel<<<NROW, 256>>>(x, n1g, n1b, p_h);
    gemm_pipe<3><<<dim3(19, 64), 256, GSMEM>>>(p_h, qkv_w, nullptr, nullptr, p_qkv,
                                               nullptr, nullptr, NROW, 3 * CDIM, CDIM, 0);
    attn_kernel<<<NB * NHD, 256, ATTN_SMEM>>>(p_qkv, p_aomain);
    gemm_pipe<3><<<dim3(7, 64), 256, GSMEM>>>(p_aomain, proj_w, proj_b, nullptr, p_o,
                                              p_xr, x, NROW, CDIM, CDIM, 0);

    // ---- BiFormer branch (3xTF32 routing path) ----
    transpose_kernel<<<dim3(25, 2, NB), dim3(32, 32)>>>(p_o, p_xT, 64, 784);
    wtrans_kernel<<<(192 * 64 + 255) / 256, 256>>>(bfqkv_w, p_wqkvT, 192, 64);
    wtrans_kernel<<<(64 * 64 + 255) / 256, 256>>>(bfout_w, p_woutT, 64, 64);
    gemm_pipe<3><<<dim3(2, M2 / 128), 256, GSMEM>>>(p_xT, p_wqkvT, bfqkv_b, nullptr,
                                                    p_bfqkv, nullptr, nullptr, M2, 192, 64, 0);
    bf_pool_kernel<<<NB * 49, 128>>>(p_bfqkv, p_qr, p_kr);
    bf_ar_kernel<<<(NB * 49 * 49 + 255) / 256, 256>>>(p_qr, p_kr, p_ar);
    bf_topk_kernel<<<(NB * 49 + 255) / 256, 256>>>(p_ar, p_idx);
    bf_attn_kernel<<<NB * 8 * 49, 128>>>(p_bfqkv, p_idx, p_bfao);
    bf_lepe_kernel<<<(NB * 784 * 64 + 255) / 256, 256>>>(p_bfqkv, bflepe_w, bflepe_b, p_bfao);
    gemm_pipe<3><<<dim3(1, M2 / 128), 256, GSMEM>>>(p_bfao, p_woutT, bfout_b, nullptr,
                                                    p_bf2, nullptr, nullptr, M2, 64, 64, 0);
    transpose_kernel<<<dim3(2, 25, NB), dim3(32, 32)>>>(p_bf2, out + OUT1, 784, 64);

    // ---- main path: LN2 + MLP (1xTF32; output0 tolerance has margin) ----
    ln_kernel<<<NROW, 256>>>(p_xr, n2g, n2b, p_h2);
    gemm_pipe<1><<<dim3(25, 64), 256, GSMEM>>>(p_h2, fc1_w, fc1_b, nullptr, p_mid,
                                               nullptr, nullptr, NROW, HID, CDIM, 1);
    gemm_pipe<1><<<dim3(7, 64), 256, GSMEM>>>(p_mid, fc2_w, fc2_b, p_xr, out,
                                              nullptr, nullptr, NROW, CDIM, HID, 0);
}

// round 6
// speedup vs baseline: 2.0823x; 1.0010x over previous
#include <cuda_runtime.h>
#include <math.h>

#define NB    128
#define NTOKN 64
#define CDIM  784
#define NHD   8
#define HD    98
#define HID   3136
#define NROW  (NB*NTOKN)      // 8192
#define M2    (NB*784)        // 100352
#define OUT1  (NROW*CDIM)     // 6422528

// ---------------- scratch (device globals; no allocation allowed) ----------
__device__ float g_h_hi  [NROW*CDIM];
__device__ float g_h_lo  [NROW*CDIM];
__device__ float g_qkv   [NROW*3*CDIM];
__device__ float g_ao_hi [NROW*CDIM];
__device__ float g_ao_lo [NROW*CDIM];
__device__ float g_o     [NROW*CDIM];
__device__ float g_xr    [NROW*CDIM];
__device__ float g_h2    [NROW*CDIM];
__device__ float g_mid   [NROW*HID];
__device__ float g_xT_hi [M2*64];
__device__ float g_xT_lo [M2*64];
__device__ float g_bfqkv [M2*192];
__device__ float g_bfao  [M2*64];
__device__ float g_bfao_hi[M2*64];
__device__ float g_bfao_lo[M2*64];
__device__ float g_bf2   [M2*64];
__device__ float g_qw_hi [CDIM*3*CDIM];
__device__ float g_qw_lo [CDIM*3*CDIM];
__device__ float g_pw_hi [CDIM*CDIM];
__device__ float g_pw_lo [CDIM*CDIM];
__device__ float g_wqkvT_hi[64*192];
__device__ float g_wqkvT_lo[64*192];
__device__ float g_woutT_hi[64*64];
__device__ float g_woutT_lo[64*64];
__device__ float g_qr    [NB*49*64];
__device__ float g_kr    [NB*49*64];
__device__ float g_ar    [NB*49*49];
__device__ int   g_topk  [NB*49*4];

// ---------------- helpers ----------------------------------------------------
__device__ __forceinline__ float f2tf32f(float x) {
    unsigned r;
    asm("cvt.rna.tf32.f32 %0, %1;" : "=r"(r) : "f"(x));
    return __uint_as_float(r);
}

__device__ __forceinline__ void mma_tf32(float& d0, float& d1, float& d2, float& d3,
                                         unsigned a0, unsigned a1, unsigned a2, unsigned a3,
                                         unsigned b0, unsigned b1) {
    asm volatile(
        "mma.sync.aligned.m16n8k8.row.col.f32.tf32.tf32.f32 "
        "{%0,%1,%2,%3}, {%4,%5,%6,%7}, {%8,%9}, {%0,%1,%2,%3};\n"
        : "+f"(d0), "+f"(d1), "+f"(d2), "+f"(d3)
        : "r"(a0), "r"(a1), "r"(a2), "r"(a3), "r"(b0), "r"(b1));
}

__device__ __forceinline__ void cp16(void* dst, const void* src, bool pred) {
    unsigned daddr = (unsigned)__cvta_generic_to_shared(dst);
    int sz = pred ? 16 : 0;
    asm volatile("cp.async.cg.shared.global [%0], [%1], 16, %2;\n"
                 :: "r"(daddr), "l"(src), "r"(sz));
}
#define CP_COMMIT() asm volatile("cp.async.commit_group;\n" ::: "memory")
#define CP_WAIT1()  asm volatile("cp.async.wait_group 1;\n" ::: "memory")
#define CP_WAIT2()  asm volatile("cp.async.wait_group 2;\n" ::: "memory")

// ---------------- gmem tf32 split: hi = rna(x), lo = rna(x - hi) ------------
__global__ void split_kernel(const float* __restrict__ in, float* __restrict__ hi,
                             float* __restrict__ lo, int n) {
    int i = blockIdx.x * blockDim.x + threadIdx.x;
    if (i < n) {
        float x = in[i];
        float h = f2tf32f(x);
        hi[i] = h;
        lo[i] = f2tf32f(x - h);
    }
}

// ---------------- LayerNorm (raw output) ------------------------------------
__global__ void ln_kernel(const float* __restrict__ x, const float* __restrict__ g,
                          const float* __restrict__ b, float* __restrict__ y) {
    int row = blockIdx.x;
    const float* xr = x + (size_t)row * CDIM;
    float* yr = y + (size_t)row * CDIM;
    float s = 0.f, s2 = 0.f;
    for (int i = threadIdx.x; i < CDIM; i += blockDim.x) {
        float v = xr[i]; s += v; s2 += v * v;
    }
    for (int o = 16; o; o >>= 1) {
        s  += __shfl_xor_sync(0xffffffffu, s,  o);
        s2 += __shfl_xor_sync(0xffffffffu, s2, o);
    }
    __shared__ float sh[16], sh2[16];
    int warp = threadIdx.x >> 5, lane = threadIdx.x & 31;
    if (lane == 0) { sh[warp] = s; sh2[warp] = s2; }
    __syncthreads();
    if (threadIdx.x == 0) {
        float t = 0.f, t2 = 0.f;
        int nw = blockDim.x >> 5;
        for (int i = 0; i < nw; i++) { t += sh[i]; t2 += sh2[i]; }
        sh[0] = t; sh2[0] = t2;
    }
    __syncthreads();
    float mean = sh[0] * (1.0f / CDIM);
    float var  = sh2[0] * (1.0f / CDIM) - mean * mean;
    float rinv = rsqrtf(var + 1e-5f);
    for (int i = threadIdx.x; i < CDIM; i += blockDim.x)
        yr[i] = (xr[i] - mean) * rinv * g[i] + b[i];
}

// ---------------- LayerNorm with split output --------------------------------
__global__ void ln_split_kernel(const float* __restrict__ x, const float* __restrict__ g,
                                const float* __restrict__ b,
                                float* __restrict__ yh, float* __restrict__ yl) {
    int row = blockIdx.x;
    const float* xr = x + (size_t)row * CDIM;
    float s = 0.f, s2 = 0.f;
    for (int i = threadIdx.x; i < CDIM; i += blockDim.x) {
        float v = xr[i]; s += v; s2 += v * v;
    }
    for (int o = 16; o; o >>= 1) {
        s  += __shfl_xor_sync(0xffffffffu, s,  o);
        s2 += __shfl_xor_sync(0xffffffffu, s2, o);
    }
    __shared__ float sh[16], sh2[16];
    int warp = threadIdx.x >> 5, lane = threadIdx.x & 31;
    if (lane == 0) { sh[warp] = s; sh2[warp] = s2; }
    __syncthreads();
    if (threadIdx.x == 0) {
        float t = 0.f, t2 = 0.f;
        int nw = blockDim.x >> 5;
        for (int i = 0; i < nw; i++) { t += sh[i]; t2 += sh2[i]; }
        sh[0] = t; sh2[0] = t2;
    }
    __syncthreads();
    float mean = sh[0] * (1.0f / CDIM);
    float var  = sh2[0] * (1.0f / CDIM) - mean * mean;
    float rinv = rsqrtf(var + 1e-5f);
    size_t base = (size_t)row * CDIM;
    for (int i = threadIdx.x; i < CDIM; i += blockDim.x) {
        float v = (xr[i] - mean) * rinv * g[i] + b[i];
        float h = f2tf32f(v);
        yh[base + i] = h;
        yl[base + i] = f2tf32f(v - h);
    }
}

#define BM 128
#define BN 128
#define BK 16

// ---------------- 1xTF32 pipelined GEMM (rna cvt at frag load, 3-stage) -----
#define GS1 ((3*BM*20 + 3*BK*136) * 4)   // 56832
__global__ void __launch_bounds__(256, 2)
gemm_pipe1(const float* __restrict__ A, const float* __restrict__ B,
           const float* __restrict__ bias, const float* __restrict__ res,
           float* __restrict__ C, int M, int N, int K, int act) {
    extern __shared__ float smraw[];
    float (*As)[BM][20]  = (float(*)[BM][20])smraw;
    float (*Bs)[BK][136] = (float(*)[BK][136])(smraw + 3 * BM * 20);

    int tid  = threadIdx.x;
    int warp = tid >> 5, lane = tid & 31;
    int wm = warp & 1, wn = warp >> 1;
    int row0 = blockIdx.y * BM, col0 = blockIdx.x * BN;

    int aRow = tid >> 2, aCol = (tid & 3) * 4;
    int bRow = tid >> 5, bCol = (tid & 31) * 4;
    bool bp = (col0 + bCol) < N;

    float acc[4][4][4];
#pragma unroll
    for (int i = 0; i < 4; i++)
#pragma unroll
        for (int j = 0; j < 4; j++)
#pragma unroll
            for (int q = 0; q < 4; q++) acc[i][j][q] = 0.f;

    int nk = K / BK;

#define PREF1(SIDX, K0) do { \
        cp16(&As[SIDX][aRow][aCol],      A + (size_t)(row0 + aRow) * K + (K0) + aCol, true); \
        cp16(&As[SIDX][aRow + 64][aCol], A + (size_t)(row0 + aRow + 64) * K + (K0) + aCol, true); \
        cp16(&Bs[SIDX][bRow][bCol],      B + (size_t)((K0) + bRow) * N + col0 + bCol, bp); \
        cp16(&Bs[SIDX][bRow + 8][bCol],  B + (size_t)((K0) + bRow + 8) * N + col0 + bCol, bp); \
    } while (0)

    PREF1(0, 0); CP_COMMIT();
    if (nk > 1) PREF1(1, BK);
    CP_COMMIT();

    int r = lane >> 2, c = lane & 3;

    for (int kt = 0; kt < nk; kt++) {
        int kn = kt + 2;
        if (kn < nk) { int sn = kn % 3; PREF1(sn, kn * BK); }
        CP_COMMIT();
        CP_WAIT2();
        __syncthreads();

        int s = kt % 3;
#pragma unroll
        for (int ks = 0; ks < 2; ks++) {
            int kk = ks * 8;
            unsigned af[4][4], bf[4][2];
#pragma unroll
            for (int mt = 0; mt < 4; mt++) {
                int m = wm * 64 + mt * 16;
                af[mt][0] = __float_as_uint(f2tf32f(As[s][m + r][kk + c]));
                af[mt][1] = __float_as_uint(f2tf32f(As[s][m + r + 8][kk + c]));
                af[mt][2] = __float_as_uint(f2tf32f(As[s][m + r][kk + c + 4]));
                af[mt][3] = __float_as_uint(f2tf32f(As[s][m + r + 8][kk + c + 4]));
            }
#pragma unroll
            for (int nt = 0; nt < 4; nt++) {
                int n = wn * 32 + nt * 8 + r;
                bf[nt][0] = __float_as_uint(f2tf32f(Bs[s][kk + c][n]));
                bf[nt][1] = __float_as_uint(f2tf32f(Bs[s][kk + c + 4][n]));
            }
#pragma unroll
            for (int mt = 0; mt < 4; mt++)
#pragma unroll
                for (int nt = 0; nt < 4; nt++)
                    mma_tf32(acc[mt][nt][0], acc[mt][nt][1], acc[mt][nt][2], acc[mt][nt][3],
                             af[mt][0], af[mt][1], af[mt][2], af[mt][3],
                             bf[nt][0], bf[nt][1]);
        }
        __syncthreads();
    }
#undef PREF1

#pragma unroll
    for (int mt = 0; mt < 4; mt++) {
        int rr0 = row0 + wm * 64 + mt * 16 + r;
#pragma unroll
        for (int nt = 0; nt < 4; nt++) {
            int cb = col0 + wn * 32 + nt * 8 + 2 * c;
#pragma unroll
            for (int half = 0; half < 2; half++) {
                int rr = rr0 + half * 8;
                float v0 = acc[mt][nt][half * 2 + 0];
                float v1 = acc[mt][nt][half * 2 + 1];
                if (bias) { if (cb < N) v0 += bias[cb]; if (cb + 1 < N) v1 += bias[cb + 1]; }
                if (act == 1) {
                    v0 = 0.5f * v0 * (1.f + erff(v0 * 0.70710678118654752f));
                    v1 = 0.5f * v1 * (1.f + erff(v1 * 0.70710678118654752f));
                }
                size_t base = (size_t)rr * N + cb;
                if (res) { if (cb < N) v0 += res[base]; if (cb + 1 < N) v1 += res[base + 1]; }
                if (cb < N)     C[base]     = v0;
                if (cb + 1 < N) C[base + 1] = v1;
            }
        }
    }
}

// ---------------- 3xTF32 GEMM with pre-split operands (2-stage) --------------
#define GS3 ((2*2*BM*20 + 2*2*BK*136) * 4)   // 75776
__global__ void __launch_bounds__(256, 2)
gemm_split3(const float* __restrict__ Ah, const float* __restrict__ Al,
            const float* __restrict__ Bh, const float* __restrict__ Bl,
            const float* __restrict__ bias, const float* __restrict__ res,
            float* __restrict__ C, float* __restrict__ C2, const float* __restrict__ res2,
            int M, int N, int K) {
    extern __shared__ float smraw[];
    float (*Ash)[BM][20]  = (float(*)[BM][20])smraw;
    float (*Asl)[BM][20]  = (float(*)[BM][20])(smraw + 2 * BM * 20);
    float (*Bsh)[BK][136] = (float(*)[BK][136])(smraw + 4 * BM * 20);
    float (*Bsl)[BK][136] = (float(*)[BK][136])(smraw + 4 * BM * 20 + 2 * BK * 136);

    int tid  = threadIdx.x;
    int warp = tid >> 5, lane = tid & 31;
    int wm = warp & 1, wn = warp >> 1;
    int row0 = blockIdx.y * BM, col0 = blockIdx.x * BN;

    int aRow = tid >> 2, aCol = (tid & 3) * 4;
    int bRow = tid >> 5, bCol = (tid & 31) * 4;
    bool bp = (col0 + bCol) < N;

    float acc[4][4][4];
#pragma unroll
    for (int i = 0; i < 4; i++)
#pragma unroll
        for (int j = 0; j < 4; j++)
#pragma unroll
            for (int q = 0; q < 4; q++) acc[i][j][q] = 0.f;

    int nk = K / BK;

#define PREF3(SIDX, K0) do { \
        size_t aoff0 = (size_t)(row0 + aRow) * K + (K0) + aCol; \
        size_t aoff1 = (size_t)(row0 + aRow + 64) * K + (K0) + aCol; \
        size_t boff0 = (size_t)((K0) + bRow) * N + col0 + bCol; \
        size_t boff1 = (size_t)((K0) + bRow + 8) * N + col0 + bCol; \
        cp16(&Ash[SIDX][aRow][aCol],      Ah + aoff0, true); \
        cp16(&Ash[SIDX][aRow + 64][aCol], Ah + aoff1, true); \
        cp16(&Asl[SIDX][aRow][aCol],      Al + aoff0, true); \
        cp16(&Asl[SIDX][aRow + 64][aCol], Al + aoff1, true); \
        cp16(&Bsh[SIDX][bRow][bCol],      Bh + boff0, bp); \
        cp16(&Bsh[SIDX][bRow + 8][bCol],  Bh + boff1, bp); \
        cp16(&Bsl[SIDX][bRow][bCol],      Bl + boff0, bp); \
        cp16(&Bsl[SIDX][bRow + 8][bCol],  Bl + boff1, bp); \
    } while (0)

    PREF3(0, 0); CP_COMMIT();
    if (nk > 1) PREF3(1, BK);
    CP_COMMIT();

    int r = lane >> 2, c = lane & 3;

    for (int kt = 0; kt < nk; kt++) {
        CP_WAIT1();
        __syncthreads();
        int s = kt & 1;
#pragma unroll
        for (int ks = 0; ks < 2; ks++) {
            int kk = ks * 8;
            unsigned afh[4][4], afl[4][4], bfh[4][2], bfl[4][2];
#pragma unroll
            for (int mt = 0; mt < 4; mt++) {
                int m = wm * 64 + mt * 16;
                afh[mt][0] = __float_as_uint(Ash[s][m + r][kk + c]);
                afh[mt][1] = __float_as_uint(Ash[s][m + r + 8][kk + c]);
                afh[mt][2] = __float_as_uint(Ash[s][m + r][kk + c + 4]);
                afh[mt][3] = __float_as_uint(Ash[s][m + r + 8][kk + c + 4]);
                afl[mt][0] = __float_as_uint(Asl[s][m + r][kk + c]);
                afl[mt][1] = __float_as_uint(Asl[s][m + r + 8][kk + c]);
                afl[mt][2] = __float_as_uint(Asl[s][m + r][kk + c + 4]);
                afl[mt][3] = __float_as_uint(Asl[s][m + r + 8][kk + c + 4]);
            }
#pragma unroll
            for (int nt = 0; nt < 4; nt++) {
                int n = wn * 32 + nt * 8 + r;
                bfh[nt][0] = __float_as_uint(Bsh[s][kk + c][n]);
                bfh[nt][1] = __float_as_uint(Bsh[s][kk + c + 4][n]);
                bfl[nt][0] = __float_as_uint(Bsl[s][kk + c][n]);
                bfl[nt][1] = __float_as_uint(Bsl[s][kk + c + 4][n]);
            }
#pragma unroll
            for (int mt = 0; mt < 4; mt++)
#pragma unroll
                for (int nt = 0; nt < 4; nt++) {
                    mma_tf32(acc[mt][nt][0], acc[mt][nt][1], acc[mt][nt][2], acc[mt][nt][3],
                             afh[mt][0], afh[mt][1], afh[mt][2], afh[mt][3],
                             bfl[nt][0], bfl[nt][1]);
                    mma_tf32(acc[mt][nt][0], acc[mt][nt][1], acc[mt][nt][2], acc[mt][nt][3],
                             afl[mt][0], afl[mt][1], afl[mt][2], afl[mt][3],
                             bfh[nt][0], bfh[nt][1]);
                    mma_tf32(acc[mt][nt][0], acc[mt][nt][1], acc[mt][nt][2], acc[mt][nt][3],
                             afh[mt][0], afh[mt][1], afh[mt][2], afh[mt][3],
                             bfh[nt][0], bfh[nt][1]);
                }
        }
        __syncthreads();
        int kn = kt + 2;
        if (kn < nk) PREF3(s, kn * BK);
        CP_COMMIT();
    }
#undef PREF3

#pragma unroll
    for (int mt = 0; mt < 4; mt++) {
        int rr0 = row0 + wm * 64 + mt * 16 + r;
#pragma unroll
        for (int nt = 0; nt < 4; nt++) {
            int cb = col0 + wn * 32 + nt * 8 + 2 * c;
#pragma unroll
            for (int half = 0; half < 2; half++) {
                int rr = rr0 + half * 8;
                float v0 = acc[mt][nt][half * 2 + 0];
                float v1 = acc[mt][nt][half * 2 + 1];
                if (bias) { if (cb < N) v0 += bias[cb]; if (cb + 1 < N) v1 += bias[cb + 1]; }
                size_t base = (size_t)rr * N + cb;
                float w0 = v0, w1 = v1;
                if (res) { if (cb < N) w0 += res[base]; if (cb + 1 < N) w1 += res[base + 1]; }
                if (cb < N)     C[base]     = w0;
                if (cb + 1 < N) C[base + 1] = w1;
                if (C2) {
                    float u0 = v0, u1 = v1;
                    if (res2) { if (cb < N) u0 += res2[base]; if (cb + 1 < N) u1 += res2[base + 1]; }
                    if (cb < N)     C2[base]     = u0;
                    if (cb + 1 < N) C2[base + 1] = u1;
                }
            }
        }
    }
}

// ---------------- fused main MHA: one block per (b, h); split output --------
#define ATTN_SMEM ((3*64*99 + 64*64) * 4)
__global__ void attn_kernel(const float* __restrict__ qkv,
                            float* __restrict__ oh, float* __restrict__ ol) {
    extern __shared__ float sm[];
    float* Qs = sm;
    float* Ks = Qs + 64 * 99;
    float* Vs = Ks + 64 * 99;
    float* Ss = Vs + 64 * 99;
    int b = blockIdx.x >> 3;
    int h = blockIdx.x & 7;
    const float* base = qkv + (size_t)b * 64 * (3 * CDIM) + h * HD;

    for (int e = threadIdx.x; e < 64 * HD; e += blockDim.x) {
        int r = e / HD, d = e % HD;
        const float* rp = base + (size_t)r * (3 * CDIM) + d;
        Qs[r * 99 + d] = rp[0];
        Ks[r * 99 + d] = rp[CDIM];
        Vs[r * 99 + d] = rp[2 * CDIM];
    }
    __syncthreads();

    const float scale = 1.0f / sqrtf(98.0f);
    for (int e = threadIdx.x; e < 4096; e += blockDim.x) {
        int i = e >> 6, j = e & 63;
        const float* qi = Qs + i * 99;
        const float* kj = Ks + j * 99;
        float a = 0.f;
#pragma unroll
        for (int d = 0; d < HD; d++) a = fmaf(qi[d], kj[d], a);
        Ss[e] = a * scale;
    }
    __syncthreads();

    int warp = threadIdx.x >> 5, lane = threadIdx.x & 31;
    for (int i = warp; i < 64; i += 8) {
        float v0 = Ss[i * 64 + lane], v1 = Ss[i * 64 + lane + 32];
        float mx = fmaxf(v0, v1);
        for (int o = 16; o; o >>= 1) mx = fmaxf(mx, __shfl_xor_sync(0xffffffffu, mx, o));
        float e0 = __expf(v0 - mx), e1 = __expf(v1 - mx);
        float s = e0 + e1;
        for (int o = 16; o; o >>= 1) s += __shfl_xor_sync(0xffffffffu, s, o);
        float inv = 1.f / s;
        Ss[i * 64 + lane]      = e0 * inv;
        Ss[i * 64 + lane + 32] = e1 * inv;
    }
    __syncthreads();

    for (int e = threadIdx.x; e < 64 * HD; e += blockDim.x) {
        int i = e / HD, d = e % HD;
        const float* p = Ss + i * 64;
        float a = 0.f;
#pragma unroll
        for (int j = 0; j < 64; j++) a = fmaf(p[j], Vs[j * 99 + d], a);
        size_t idx = ((size_t)b * 64 + i) * CDIM + h * HD + d;
        float hh = f2tf32f(a);
        oh[idx] = hh;
        ol[idx] = f2tf32f(a - hh);
    }
}

// ---------------- transpose with split output: [b][64][784] -> [b][784][64] -
__global__ void transpose_split_kernel(const float* __restrict__ in,
                                       float* __restrict__ oh, float* __restrict__ ol) {
    __shared__ float tile[32][33];
    int b = blockIdx.z;
    int r0 = blockIdx.y * 32, c0 = blockIdx.x * 32;
    const float* ib = in + (size_t)b * 64 * 784;
    int r = r0 + threadIdx.y, c = c0 + threadIdx.x;
    if (r < 64 && c < 784) tile[threadIdx.y][threadIdx.x] = ib[(size_t)r * 784 + c];
    __syncthreads();
    int rr = r0 + threadIdx.x, cc = c0 + threadIdx.y;
    if (rr < 64 && cc < 784) {
        float v = tile[threadIdx.x][threadIdx.y];
        float h = f2tf32f(v);
        size_t o = (size_t)b * 64 * 784 + (size_t)cc * 64 + rr;
        oh[o] = h;
        ol[o] = f2tf32f(v - h);
    }
}

// ---------------- plain transpose: [bt][R][Cc] -> [bt][Cc][R] ----------------
__global__ void transpose_kernel(const float* __restrict__ in, float* __restrict__ out,
                                 int R, int Cc) {
    __shared__ float tile[32][33];
    int b = blockIdx.z;
    int r0 = blockIdx.y * 32, c0 = blockIdx.x * 32;
    const float* ib = in + (size_t)b * R * Cc;
    float* ob = out + (size_t)b * R * Cc;
    int r = r0 + threadIdx.y, c = c0 + threadIdx.x;
    if (r < R && c < Cc) tile[threadIdx.y][threadIdx.x] = ib[(size_t)r * Cc + c];
    __syncthreads();
    int rr = r0 + threadIdx.x, cc = c0 + threadIdx.y;
    if (rr < R && cc < Cc) ob[(size_t)cc * R + rr] = tile[threadIdx.x][threadIdx.y];
}

// ---------------- weight transpose + split: w[O][Cn] -> wt{h,l}[Cn][O] ------
__global__ void wtrans_split_kernel(const float* __restrict__ w,
                                    float* __restrict__ wth, float* __restrict__ wtl,
                                    int O, int Cn) {
    int e = blockIdx.x * blockDim.x + threadIdx.x;
    if (e < O * Cn) {
        int o = e / Cn, c = e % Cn;
        float v = w[e];
        float h = f2tf32f(v);
        wth[c * O + o] = h;
        wtl[c * O + o] = f2tf32f(v - h);
    }
}

// ---------------- BiFormer: region mean-pool of q/k -------------------------
__global__ void bf_pool_kernel(const float* __restrict__ qkvt,
                               float* __restrict__ qr, float* __restrict__ kr) {
    int br = blockIdx.x;
    int b = br / 49, r = br % 49;
    int rh = r / 7, rw = r % 7;
    int tid = threadIdx.x;
    int c = tid & 63;
    int off = (tid >= 64) ? 64 : 0;
    int hw0 = (rh * 4) * 28 + rw * 4;
    float s = 0.f;
#pragma unroll
    for (int p = 0; p < 4; p++)
#pragma unroll
        for (int q = 0; q < 4; q++) {
            int hw = hw0 + p * 28 + q;
            s += qkvt[((size_t)b * 784 + hw) * 192 + off + c];
        }
    float* dst = (tid >= 64) ? kr : qr;
    dst[((size_t)b * 49 + r) * 64 + c] = s * (1.0f / 16.0f);
}

// ---------------- region affinity ---------------------------------------------
__global__ void bf_ar_kernel(const float* __restrict__ qr, const float* __restrict__ kr,
                             float* __restrict__ ar) {
    int idx = blockIdx.x * blockDim.x + threadIdx.x;
    if (idx >= NB * 49 * 49) return;
    int s = idx % 49, r = (idx / 49) % 49, b = idx / (49 * 49);
    const float* qp = qr + ((size_t)b * 49 + r) * 64;
    const float* kp = kr + ((size_t)b * 49 + s) * 64;
    float a = 0.f;
#pragma unroll
    for (int c = 0; c < 64; c++) a = fmaf(qp[c], kp[c], a);
    ar[idx] = a;
}

// ---------------- top-4 per (b, r) -------------------------------------------
__global__ void bf_topk_kernel(const float* __restrict__ ar, int* __restrict__ idx) {
    int t = blockIdx.x * blockDim.x + threadIdx.x;
    if (t >= NB * 49) return;
    float v[49];
    const float* row = ar + (size_t)t * 49;
#pragma unroll
    for (int s = 0; s < 49; s++) v[s] = row[s];
    for (int k = 0; k < 4; k++) {
        float best = -3.4e38f; int bi = 0;
        for (int s = 0; s < 49; s++)
            if (v[s] > best) { best = v[s]; bi = s; }
        idx[t * 4 + k] = bi;
        v[bi] = -3.4e38f;
    }
}

// ---------------- BiFormer region attention ----------------------------------
__global__ void bf_attn_kernel(const float* __restrict__ qkvt, const int* __restrict__ idx,
                               float* __restrict__ ao) {
    __shared__ float Qs[16][8], Ks[64][9], Vs[64][9], S[16][64];
    __shared__ int sreg[4];
    int r = blockIdx.x % 49;
    int m = (blockIdx.x / 49) & 7;
    int b = blockIdx.x / (49 * 8);
    int tid = threadIdx.x;
    int rh = r / 7, rw = r % 7;

    if (tid < 4) sreg[tid] = idx[((size_t)b * 49 + r) * 4 + tid];
    {
        int p = tid >> 3, d = tid & 7;
        int hw = (rh * 4 + (p >> 2)) * 28 + rw * 4 + (p & 3);
        Qs[p][d] = qkvt[((size_t)b * 784 + hw) * 192 + m * 8 + d];
    }
    __syncthreads();

    for (int e = tid; e < 512; e += 128) {
        int slot = e >> 3, d = e & 7;
        int t = slot >> 4, s = slot & 15;
        int sr = sreg[t];
        int hw = ((sr / 7) * 4 + (s >> 2)) * 28 + (sr % 7) * 4 + (s & 3);
        const float* p = qkvt + ((size_t)b * 784 + hw) * 192 + m * 8 + d;
        Ks[slot][d] = p[64];
        Vs[slot][d] = p[128];
    }
    __syncthreads();

    for (int e = tid; e < 1024; e += 128) {
        int i = e >> 6, j = e & 63;
        float a = 0.f;
#pragma unroll
        for (int d = 0; d < 8; d++) a = fmaf(Qs[i][d], Ks[j][d], a);
        S[i][j] = a * 0.125f;
    }
    __syncthreads();

    int warp = tid >> 5, lane = tid & 31;
    for (int i = warp; i < 16; i += 4) {
        float v0 = S[i][lane], v1 = S[i][lane + 32];
        float mx = fmaxf(v0, v1);
        for (int o = 16; o; o >>= 1) mx = fmaxf(mx, __shfl_xor_sync(0xffffffffu, mx, o));
        float e0 = __expf(v0 - mx), e1 = __expf(v1 - mx);
        float s = e0 + e1;
        for (int o = 16; o; o >>= 1) s += __shfl_xor_sync(0xffffffffu, s, o);
        float inv = 1.f / s;
        S[i][lane] = e0 * inv;
        S[i][lane + 32] = e1 * inv;
    }
    __syncthreads();

    {
        int i = tid >> 3, d = tid & 7;
        float a = 0.f;
#pragma unroll
        for (int j = 0; j < 64; j++) a = fmaf(S[i][j], Vs[j][d], a);
        int hw = (rh * 4 + (i >> 2)) * 28 + rw * 4 + (i & 3);
        ao[((size_t)b * 784 + hw) * 64 + m * 8 + d] = a;
    }
}

// ---------------- LePE: adds 3x3 dw conv to ao, writes split hi/lo ----------
__global__ void bf_lepe_split_kernel(const float* __restrict__ qkvt,
                                     const float* __restrict__ w,
                                     const float* __restrict__ bias,
                                     const float* __restrict__ ao,
                                     float* __restrict__ aoh, float* __restrict__ aol) {
    int e = blockIdx.x * blockDim.x + threadIdx.x;
    if (e >= NB * 784 * 64) return;
    int c  = e & 63;
    int hw = (e >> 6) % 784;
    int b  = e / (784 * 64);
    int h = hw / 28, wq = hw % 28;
    float acc = bias[c];
#pragma unroll
    for (int i = 0; i < 3; i++) {
        int hh = h + i - 1;
        if (hh < 0 || hh >= 28) continue;
#pragma unroll
        for (int j = 0; j < 3; j++) {
            int ww = wq + j - 1;
            if (ww < 0 || ww >= 28) continue;
            acc = fmaf(qkvt[((size_t)b * 784 + hh * 28 + ww) * 192 + 128 + c],
                       w[c * 9 + i * 3 + j], acc);
        }
    }
    float v = ao[e] + acc;
    float hh2 = f2tf32f(v);
    aoh[e] = hh2;
    aol[e] = f2tf32f(v - hh2);
}

// ============================================================================
extern "C" void kernel_launch(void* const* d_in, const int* in_sizes, int n_in,
                              void* d_out, int out_size) {
    const float* x        = (const float*)d_in[0];
    const float* n1g      = (const float*)d_in[1];
    const float* n1b      = (const float*)d_in[2];
    const float* qkv_w    = (const float*)d_in[3];
    const float* proj_w   = (const float*)d_in[4];
    const float* proj_b   = (const float*)d_in[5];
    const float* n2g      = (const float*)d_in[6];
    const float* n2b      = (const float*)d_in[7];
    const float* fc1_w    = (const float*)d_in[8];
    const float* fc1_b    = (const float*)d_in[9];
    const float* fc2_w    = (const float*)d_in[10];
    const float* fc2_b    = (const float*)d_in[11];
    const float* bfqkv_w  = (const float*)d_in[12];
    const float* bfqkv_b  = (const float*)d_in[13];
    const float* bflepe_w = (const float*)d_in[14];
    const float* bflepe_b = (const float*)d_in[15];
    const float* bfout_w  = (const float*)d_in[16];
    const float* bfout_b  = (const float*)d_in[17];
    float* out = (float*)d_out;

    float *p_hh, *p_hl, *p_qkv, *p_aoh, *p_aol, *p_o, *p_xr, *p_h2, *p_mid;
    float *p_xTh, *p_xTl, *p_bfqkv, *p_bfao, *p_bfaoh, *p_bfaol, *p_bf2;
    float *p_qwh, *p_qwl, *p_pwh, *p_pwl, *p_wqh, *p_wql, *p_woh, *p_wol;
    float *p_qr, *p_kr, *p_ar;
    int* p_idx;
    cudaGetSymbolAddress((void**)&p_hh,    g_h_hi);
    cudaGetSymbolAddress((void**)&p_hl,    g_h_lo);
    cudaGetSymbolAddress((void**)&p_qkv,   g_qkv);
    cudaGetSymbolAddress((void**)&p_aoh,   g_ao_hi);
    cudaGetSymbolAddress((void**)&p_aol,   g_ao_lo);
    cudaGetSymbolAddress((void**)&p_o,     g_o);
    cudaGetSymbolAddress((void**)&p_xr,    g_xr);
    cudaGetSymbolAddress((void**)&p_h2,    g_h2);
    cudaGetSymbolAddress((void**)&p_mid,   g_mid);
    cudaGetSymbolAddress((void**)&p_xTh,   g_xT_hi);
    cudaGetSymbolAddress((void**)&p_xTl,   g_xT_lo);
    cudaGetSymbolAddress((void**)&p_bfqkv, g_bfqkv);
    cudaGetSymbolAddress((void**)&p_bfao,  g_bfao);
    cudaGetSymbolAddress((void**)&p_bfaoh, g_bfao_hi);
    cudaGetSymbolAddress((void**)&p_bfaol, g_bfao_lo);
    cudaGetSymbolAddress((void**)&p_bf2,   g_bf2);
    cudaGetSymbolAddress((void**)&p_qwh,   g_qw_hi);
    cudaGetSymbolAddress((void**)&p_qwl,   g_qw_lo);
    cudaGetSymbolAddress((void**)&p_pwh,   g_pw_hi);
    cudaGetSymbolAddress((void**)&p_pwl,   g_pw_lo);
    cudaGetSymbolAddress((void**)&p_wqh,   g_wqkvT_hi);
    cudaGetSymbolAddress((void**)&p_wql,   g_wqkvT_lo);
    cudaGetSymbolAddress((void**)&p_woh,   g_woutT_hi);
    cudaGetSymbolAddress((void**)&p_wol,   g_woutT_lo);
    cudaGetSymbolAddress((void**)&p_qr,    g_qr);
    cudaGetSymbolAddress((void**)&p_kr,    g_kr);
    cudaGetSymbolAddress((void**)&p_ar,    g_ar);
    cudaGetSymbolAddress((void**)&p_idx,   g_topk);

    cudaFuncSetAttribute(attn_kernel, cudaFuncAttributeMaxDynamicSharedMemorySize, ATTN_SMEM);
    cudaFuncSetAttribute(gemm_pipe1,  cudaFuncAttributeMaxDynamicSharedMemorySize, GS1);
    cudaFuncSetAttribute(gemm_split3, cudaFuncAttributeMaxDynamicSharedMemorySize, GS3);

    // ---- weight splits (independent; cheap) ----
    split_kernel<<<(CDIM * 3 * CDIM + 255) / 256, 256>>>(qkv_w, p_qwh, p_qwl, CDIM * 3 * CDIM);
    split_kernel<<<(CDIM * CDIM + 255) / 256, 256>>>(proj_w, p_pwh, p_pwl, CDIM * CDIM);
    wtrans_split_kernel<<<(192 * 64 + 255) / 256, 256>>>(bfqkv_w, p_wqh, p_wql, 192, 64);
    wtrans_split_kernel<<<(64 * 64 + 255) / 256, 256>>>(bfout_w, p_woh, p_wol, 64, 64);

    // ---- main path up through proj (3xTF32 on pre-split operands) ----
    ln_split_kernel<<<NROW, 256>>>(x, n1g, n1b, p_hh, p_hl);
    gemm_split3<<<dim3(19, 64), 256, GS3>>>(p_hh, p_hl, p_qwh, p_qwl, nullptr, nullptr,
                                            p_qkv, nullptr, nullptr, NROW, 3 * CDIM, CDIM);
    attn_kernel<<<NB * NHD, 256, ATTN_SMEM>>>(p_qkv, p_aoh, p_aol);
    gemm_split3<<<dim3(7, 64), 256, GS3>>>(p_aoh, p_aol, p_pwh, p_pwl, proj_b, nullptr,
                                           p_o, p_xr, x, NROW, CDIM, CDIM);

    // ---- BiFormer branch ----
    transpose_split_kernel<<<dim3(25, 2, NB), dim3(32, 32)>>>(p_o, p_xTh, p_xTl);
    gemm_split3<<<dim3(2, M2 / 128), 256, GS3>>>(p_xTh, p_xTl, p_wqh, p_wql, bfqkv_b, nullptr,
                                                 p_bfqkv, nullptr, nullptr, M2, 192, 64);
    bf_pool_kernel<<<NB * 49, 128>>>(p_bfqkv, p_qr, p_kr);
    bf_ar_kernel<<<(NB * 49 * 49 + 255) / 256, 256>>>(p_qr, p_kr, p_ar);
    bf_topk_kernel<<<(NB * 49 + 255) / 256, 256>>>(p_ar, p_idx);
    bf_attn_kernel<<<NB * 8 * 49, 128>>>(p_bfqkv, p_idx, p_bfao);
    bf_lepe_split_kernel<<<(NB * 784 * 64 + 255) / 256, 256>>>(p_bfqkv, bflepe_w, bflepe_b,
                                                               p_bfao, p_bfaoh, p_bfaol);
    gemm_split3<<<dim3(1, M2 / 128), 256, GS3>>>(p_bfaoh, p_bfaol, p_woh, p_wol, bfout_b,
                                                 nullptr, p_bf2, nullptr, nullptr, M2, 64, 64);
    transpose_kernel<<<dim3(2, 25, NB), dim3(32, 32)>>>(p_bf2, out + OUT1, 784, 64);

    // ---- main path: LN2 + MLP (1xTF32) ----
    ln_kernel<<<NROW, 256>>>(p_xr, n2g, n2b, p_h2);
    gemm_pipe1<<<dim3(25, 64), 256, GS1>>>(p_h2, fc1_w, fc1_b, nullptr, p_mid,
                                           NROW, HID, CDIM, 1);
    gemm_pipe1<<<dim3(7, 64), 256, GS1>>>(p_mid, fc2_w, fc2_b, p_xr, out,
                                          NROW, CDIM, HID, 0);
}